// round 9
// baseline (speedup 1.0000x reference)
#include <cuda_runtime.h>
#include <cmath>
#include <cstdint>

#define S_   1024
#define B_   4
#define D_   1024
#define H_   16
#define HD_  64
#define DFF_ 4096
#define NTOK 4096   // S_*B_

// ---------------- device-global scratch (no allocations allowed) ----------------
__device__ float g_src2 [NTOK * D_];     // LN1(src)           (tf32-rounded)
__device__ float g_qk   [NTOK * D_];     // LN1(src) + pos     (tf32-rounded)
__device__ float g_q    [NTOK * D_];     // [B,H,S,HD], alpha/8 folded, tf32
__device__ float g_k    [NTOK * D_];     // [B,H,S,HD], tf32
__device__ float g_v    [NTOK * D_];     // [B,H,S,HD], tf32
__device__ float g_ctx  [NTOK * D_];     // attention output, [S,B,D] (tf32)
__device__ float g_res1 [NTOK * D_];     // src + attn_out
__device__ float g_src2b[NTOK * D_];     // LN2(res1)          (tf32)
__device__ float g_h    [NTOK * DFF_];   // relu(ffn1)         (tf32)
__device__ float g_wi   [3 * D_ * D_];   // quantized in_proj_w  (integer-valued)
__device__ float g_wo   [D_ * D_];       // quantized out_proj_w (integer-valued)
__device__ float g_w1   [DFF_ * D_];     // quantized w1         (integer-valued)
__device__ float g_w2   [D_ * DFF_];     // quantized w2         (integer-valued)
__device__ float g_alphas[4];            // effective LSQ scales (in, out, w1, w2)

// ================= helpers =================
__device__ __forceinline__ uint32_t smem_u32(const void* p) {
    uint32_t a;
    asm("{ .reg .u64 t; cvta.to.shared.u64 t, %1; cvt.u32.u64 %0, t; }" : "=r"(a) : "l"(p));
    return a;
}
__device__ __forceinline__ float to_tf32(float x) {
    uint32_t r;
    asm("cvt.rna.tf32.f32 %0, %1;" : "=r"(r) : "f"(x));
    return __uint_as_float(r);
}
__device__ __forceinline__ void cp_async16(uint32_t saddr, const void* gaddr) {
    asm volatile("cp.async.cg.shared.global [%0], [%1], 16;" :: "r"(saddr), "l"(gaddr));
}
#define CP_COMMIT()  asm volatile("cp.async.commit_group;" ::: "memory")
#define CP_WAIT(n)   asm volatile("cp.async.wait_group %0;" :: "n"(n) : "memory")

// mma.sync m16n8k8 tf32
__device__ __forceinline__ void mma_tf32(float* d, const uint32_t* a, const uint32_t* b) {
    asm volatile(
        "mma.sync.aligned.m16n8k8.row.col.f32.tf32.tf32.f32 "
        "{%0,%1,%2,%3}, {%4,%5,%6,%7}, {%8,%9}, {%0,%1,%2,%3};"
        : "+f"(d[0]), "+f"(d[1]), "+f"(d[2]), "+f"(d[3])
        : "r"(a[0]), "r"(a[1]), "r"(a[2]), "r"(a[3]), "r"(b[0]), "r"(b[1]));
}
// ldmatrix x4: b16 lane mapping == tf32 fragment mapping when regs are read as tf32 words
__device__ __forceinline__ void ldmx4(uint32_t* r, uint32_t addr) {
    asm volatile("ldmatrix.sync.aligned.m8n8.x4.shared.b16 {%0,%1,%2,%3}, [%4];"
        : "=r"(r[0]), "=r"(r[1]), "=r"(r[2]), "=r"(r[3]) : "r"(addr));
}

// ---------------- LSQ weight quantization: all 4 matrices, one launch, float4 ----------------
#define NWI (3 * D_ * D_)
#define NWO (D_ * D_)
#define NW1 (DFF_ * D_)
#define NW2 (D_ * DFF_)
__global__ void quant_all_kernel(
    const float* __restrict__ wi, const float* __restrict__ ai,
    const float* __restrict__ wo, const float* __restrict__ ao,
    const float* __restrict__ w1, const float* __restrict__ a1,
    const float* __restrict__ w2, const float* __restrict__ a2)
{
    int i = blockIdx.x * blockDim.x + threadIdx.x;     // float4 index
    const float* w; const float* alp; float* out; float gg; int slot; int li;
    if (i < NWI / 4) {
        w = wi; alp = ai; out = g_wi; li = i; slot = 0;
        gg = 2.1308894e-4f;                           // 1/sqrt(NWI*7)
    } else if (i < (NWI + NWO) / 4) {
        w = wo; alp = ao; out = g_wo; li = i - NWI / 4; slot = 1;
        gg = 3.6908489e-4f;                           // 1/sqrt(NWO*7)
    } else if (i < (NWI + NWO + NW1) / 4) {
        w = w1; alp = a1; out = g_w1; li = i - (NWI + NWO) / 4; slot = 2;
        gg = 1.8454244e-4f;                           // 1/sqrt(NW1*7)
    } else if (i < (NWI + NWO + NW1 + NW2) / 4) {
        w = w2; alp = a2; out = g_w2; li = i - (NWI + NWO + NW1) / 4; slot = 3;
        gg = 1.8454244e-4f;                           // 1/sqrt(NW2*7)
    } else return;
    float al = alp[0];
    float ag = al * gg;
    float a  = ag + (al - ag);
    float inv = 1.0f / a;
    float4 v = ((const float4*)w)[li];
    float4 o;
    o.x = rintf(fminf(fmaxf(v.x * inv, -8.0f), 7.0f));
    o.y = rintf(fminf(fmaxf(v.y * inv, -8.0f), 7.0f));
    o.z = rintf(fminf(fmaxf(v.z * inv, -8.0f), 7.0f));
    o.w = rintf(fminf(fmaxf(v.w * inv, -8.0f), 7.0f));
    ((float4*)out)[li] = o;
    if (li == 0) g_alphas[slot] = a;
}

// ---------------- LayerNorm (one block per row of 1024); outputs tf32-rounded ----------------
__global__ __launch_bounds__(256) void ln_kernel(
    const float* __restrict__ x, const float* __restrict__ pos,
    const float* __restrict__ gamma, const float* __restrict__ beta,
    float* __restrict__ y, float* __restrict__ yp)
{
    int row = blockIdx.x;
    int t   = threadIdx.x;
    const float4* xr = (const float4*)(x + (size_t)row * D_);
    float4 v = xr[t];
    float s  = v.x + v.y + v.z + v.w;
    float ss = v.x * v.x + v.y * v.y + v.z * v.z + v.w * v.w;
#pragma unroll
    for (int o = 16; o > 0; o >>= 1) {
        s  += __shfl_xor_sync(0xFFFFFFFFu, s,  o);
        ss += __shfl_xor_sync(0xFFFFFFFFu, ss, o);
    }
    __shared__ float ws[8], wss[8], fin[2];
    int w = t >> 5;
    if ((t & 31) == 0) { ws[w] = s; wss[w] = ss; }
    __syncthreads();
    if (t == 0) {
        float a = 0.f, b = 0.f;
#pragma unroll
        for (int i = 0; i < 8; i++) { a += ws[i]; b += wss[i]; }
        float m   = a * (1.0f / D_);
        float var = b * (1.0f / D_) - m * m;
        fin[0] = m;
        fin[1] = rsqrtf(var + 1e-5f);
    }
    __syncthreads();
    float m = fin[0], r = fin[1];
    float4 g4 = ((const float4*)gamma)[t];
    float4 b4 = ((const float4*)beta)[t];
    float4 o;
    o.x = (v.x - m) * r * g4.x + b4.x;
    o.y = (v.y - m) * r * g4.y + b4.y;
    o.z = (v.z - m) * r * g4.z + b4.z;
    o.w = (v.w - m) * r * g4.w + b4.w;
    float4 ot;
    ot.x = to_tf32(o.x); ot.y = to_tf32(o.y); ot.z = to_tf32(o.z); ot.w = to_tf32(o.w);
    ((float4*)(y + (size_t)row * D_))[t] = ot;
    if (yp) {
        float4 p = ((const float4*)(pos + (size_t)row * D_))[t];
        float4 q;
        q.x = to_tf32(o.x + p.x); q.y = to_tf32(o.y + p.y);
        q.z = to_tf32(o.z + p.z); q.w = to_tf32(o.w + p.w);
        ((float4*)(yp + (size_t)row * D_))[t] = q;
    }
}

// =============== mma.sync tf32 GEMM, ldmatrix fragments, single-barrier 3-stage pipeline ===============
// CTA tile 128x128, BK=32, 8 warps (2x4), warp tile 64x32.
#define GSTRIDE 36                       // floats/row: 16B-aligned, 36%32=4 -> ldmatrix conflict-free
#define ATILE   (128 * GSTRIDE * 4)      // 18432 B per A (or B) tile
#define STAGE   (2 * ATILE)              // 36864 B
#define NSTAGE  3
#define SM_TOTAL (NSTAGE * STAGE)        // 110592 B

template <int EPI>
__global__ __launch_bounds__(256) void mma_gemm(
    const float* __restrict__ A, const float* __restrict__ A2,
    const float* __restrict__ W, const float* __restrict__ bias,
    const float* __restrict__ resid, float* __restrict__ C,
    int K, int Nn, const float* __restrict__ alpha)
{
    extern __shared__ char smem[];
    uint32_t sb = smem_u32(smem);
    int tid = threadIdx.x;
    int wid = tid >> 5;
    int lane = tid & 31;
    int g  = lane >> 2;
    int t4 = lane & 3;
    int q3 = lane >> 3;       // ldmatrix quadrant
    int rin = lane & 7;
    int warp_m = wid >> 2;
    int warp_n = wid & 3;

    int brow = blockIdx.y * 128;
    int bcol = blockIdx.x * 128;
    const float* Ain = (EPI == 0 && bcol >= 2 * D_) ? A2 : A;

    // cp.async mapping: thread t -> tile row t>>1, 16-float half (t&1)
    int lrow = tid >> 1;
    int lhalf = tid & 1;
    const float* agp = Ain + (size_t)(brow + lrow) * K + lhalf * 16;
    const float* wgp = W   + (size_t)(bcol + lrow) * K + lhalf * 16;
    uint32_t sa = sb + lrow * (GSTRIDE * 4) + lhalf * 64;
    uint32_t sw = sa + ATILE;

    // ldmatrix per-lane base offsets
    uint32_t a_lm = sb + ((warp_m * 64 + (q3 & 1) * 8 + rin) * GSTRIDE) * 4 + (q3 >> 1) * 16;
    uint32_t b_lm = sb + ATILE + ((warp_n * 32 + (q3 >> 1) * 8 + rin) * GSTRIDE) * 4 + (q3 & 1) * 16;

    float acc[4][4][4];
#pragma unroll
    for (int i = 0; i < 4; i++)
#pragma unroll
        for (int j = 0; j < 4; j++)
#pragma unroll
            for (int e = 0; e < 4; e++) acc[i][j][e] = 0.f;

    const int nch = K / 32;

#define ISSUE(c, s) do {                                              \
        int k0_ = (c) * 32;                                           \
        uint32_t so_ = (uint32_t)(s) * STAGE;                         \
        _Pragma("unroll")                                             \
        for (int q_ = 0; q_ < 4; q_++) {                              \
            cp_async16(sa + so_ + q_ * 16, agp + k0_ + q_ * 4);       \
            cp_async16(sw + so_ + q_ * 16, wgp + k0_ + q_ * 4);       \
        }                                                             \
    } while (0)

    // prologue: 2 chunks in flight
    ISSUE(0, 0); CP_COMMIT();
    ISSUE(1, 1); CP_COMMIT();
    CP_WAIT(1);                     // chunk 0 resident
    __syncthreads();

    for (int i = 0; i < nch; i++) {
        // issue chunk i+2 into buffer (i+2)%3 == (i-1)%3, consumed at iter i-1
        // and protected by the barrier at the end of iter i-1.
        if (i + 2 < nch) ISSUE(i + 2, (i + 2) % NSTAGE);
        CP_COMMIT();                // exactly one group per iteration

        int s = i % NSTAGE;
        uint32_t ab = a_lm + (uint32_t)s * STAGE;
        uint32_t bb = b_lm + (uint32_t)s * STAGE;
#pragma unroll
        for (int ks = 0; ks < 4; ks++) {
            uint32_t af[4][4], bq[2][4];
#pragma unroll
            for (int mt = 0; mt < 4; mt++)
                ldmx4(af[mt], ab + mt * (16 * GSTRIDE * 4) + ks * 32);
#pragma unroll
            for (int pr = 0; pr < 2; pr++)
                ldmx4(bq[pr], bb + pr * (16 * GSTRIDE * 4) + ks * 32);
#pragma unroll
            for (int mt = 0; mt < 4; mt++) {
                mma_tf32(acc[mt][0], af[mt], &bq[0][0]);
                mma_tf32(acc[mt][1], af[mt], &bq[0][2]);
                mma_tf32(acc[mt][2], af[mt], &bq[1][0]);
                mma_tf32(acc[mt][3], af[mt], &bq[1][2]);
            }
        }

        // end-of-iter: chunk i+1 resident, all warps done reading buffer s
        CP_WAIT(1);
        __syncthreads();
    }
#undef ISSUE

    float scale = __ldg(alpha);
#pragma unroll
    for (int mt = 0; mt < 4; mt++) {
        int r0 = brow + warp_m * 64 + mt * 16 + g;
#pragma unroll
        for (int half = 0; half < 2; half++) {
            int rr = r0 + half * 8;
#pragma unroll
            for (int nt = 0; nt < 4; nt++) {
                int c = bcol + warp_n * 32 + nt * 8 + t4 * 2;
                float v0 = acc[mt][nt][half * 2 + 0];
                float v1 = acc[mt][nt][half * 2 + 1];
                if (EPI == 0) {
                    int region = bcol >> 10;
                    float sc = (region == 0) ? scale * 0.125f : scale;
                    float* dst0 = (region == 0) ? g_q : (region == 1) ? g_k : g_v;
                    int s  = rr >> 2;
                    int bb = rr & 3;
                    int cd = c & 1023;
                    int h  = cd >> 6, d = cd & 63;
                    float2 o = make_float2(to_tf32(v0 * sc), to_tf32(v1 * sc));
                    *(float2*)(dst0 + (((size_t)bb * H_ + h) * S_ + s) * HD_ + d) = o;
                } else {
                    float* crow = C + (size_t)rr * Nn + c;
                    v0 *= scale; v1 *= scale;
                    if (EPI == 2) {
                        float2 bb = *(const float2*)(bias + c);
                        v0 = to_tf32(fmaxf(v0 + bb.x, 0.f));
                        v1 = to_tf32(fmaxf(v1 + bb.y, 0.f));
                    }
                    if (EPI == 3) {
                        float2 bb = *(const float2*)(bias + c);
                        float2 rv = *(const float2*)(resid + (size_t)rr * Nn + c);
                        v0 += bb.x + rv.x; v1 += bb.y + rv.y;
                    }
                    if (EPI == 1) {
                        float2 rv = *(const float2*)(resid + (size_t)rr * Nn + c);
                        v0 += rv.x; v1 += rv.y;
                    }
                    *(float2*)crow = make_float2(v0, v1);
                }
            }
        }
    }
}

// =============== Flash attention on mma.sync tf32 + ldmatrix ===============
// 256 threads / 8 warps; block = 128 queries; warp owns 16 rows; 16 key tiles of 64.
#define KSTR 68                               // K/P stride: 68%32=4 -> ldmatrix conflict-free
#define VSTR 72                               // V stride:   72%32=8 -> transposed scalar reads conflict-free
#define ASM_K 0                               // Ks: 64 x 68
#define ASM_V (64 * KSTR)                     // Vs: 64 x 72
#define ASM_P (64 * KSTR + 64 * VSTR)         // Ps: 128 x 68
#define ASM_TOTAL ((64 * KSTR + 64 * VSTR + 128 * KSTR) * 4)   // 70656 B

__global__ __launch_bounds__(256) void attn_mma_kernel()
{
    extern __shared__ float sm[];
    float* Ks = sm + ASM_K;
    float* Vs = sm + ASM_V;
    float* Ps = sm + ASM_P;
    uint32_t sb = smem_u32(sm);

    int tid  = threadIdx.x;
    int wid  = tid >> 5;
    int lane = tid & 31;
    int g    = lane >> 2;
    int t4   = lane & 3;
    int q3   = lane >> 3;
    int rin  = lane & 7;
    int bh   = blockIdx.y;
    int q0   = blockIdx.x * 128;

    const float* Qb = g_q + ((size_t)bh * S_ + q0 + wid * 16) * HD_;
    uint32_t qf[8][4];
#pragma unroll
    for (int ks = 0; ks < 8; ks++) {
        qf[ks][0] = __float_as_uint(Qb[g * HD_ + ks * 8 + t4]);
        qf[ks][1] = __float_as_uint(Qb[(g + 8) * HD_ + ks * 8 + t4]);
        qf[ks][2] = __float_as_uint(Qb[g * HD_ + ks * 8 + t4 + 4]);
        qf[ks][3] = __float_as_uint(Qb[(g + 8) * HD_ + ks * 8 + t4 + 4]);
    }

    float ctx[8][4];
#pragma unroll
    for (int nt = 0; nt < 8; nt++)
#pragma unroll
        for (int e = 0; e < 4; e++) ctx[nt][e] = 0.f;
    float m0 = -1e30f, m1 = -1e30f, l0 = 0.f, l1 = 0.f;

    const float* kbase = g_k + (size_t)bh * S_ * HD_;
    const float* vbase = g_v + (size_t)bh * S_ * HD_;
    float* pw = Ps + (wid * 16) * KSTR;

    uint32_t k_lm = sb + (ASM_K + ((q3 >> 1) * 8 + rin) * KSTR) * 4 + (q3 & 1) * 16;
    uint32_t p_lm = sb + (ASM_P + (wid * 16 + (q3 & 1) * 8 + rin) * KSTR) * 4 + (q3 >> 1) * 16;

    for (int kt = 0; kt < 16; kt++) {
        __syncthreads();
#pragma unroll
        for (int i = 0; i < 4; i++) {
            int idx = i * 256 + tid;
            int r = idx >> 4, c4 = (idx & 15) * 4;
            *(float4*)(Ks + r * KSTR + c4) =
                *(const float4*)(kbase + (size_t)(kt * 64 + r) * HD_ + c4);
            *(float4*)(Vs + r * VSTR + c4) =
                *(const float4*)(vbase + (size_t)(kt * 64 + r) * HD_ + c4);
        }
        __syncthreads();

        float sacc[8][4];
#pragma unroll
        for (int nt = 0; nt < 8; nt++)
#pragma unroll
            for (int e = 0; e < 4; e++) sacc[nt][e] = 0.f;
#pragma unroll
        for (int ks = 0; ks < 8; ks++) {
#pragma unroll
            for (int pr = 0; pr < 4; pr++) {
                uint32_t kq[4];
                ldmx4(kq, k_lm + pr * (16 * KSTR * 4) + ks * 32);
                mma_tf32(sacc[pr * 2 + 0], qf[ks], &kq[0]);
                mma_tf32(sacc[pr * 2 + 1], qf[ks], &kq[2]);
            }
        }

        float mx0 = -1e30f, mx1 = -1e30f;
#pragma unroll
        for (int nt = 0; nt < 8; nt++) {
            mx0 = fmaxf(mx0, fmaxf(sacc[nt][0], sacc[nt][1]));
            mx1 = fmaxf(mx1, fmaxf(sacc[nt][2], sacc[nt][3]));
        }
        mx0 = fmaxf(mx0, __shfl_xor_sync(0xFFFFFFFFu, mx0, 1));
        mx0 = fmaxf(mx0, __shfl_xor_sync(0xFFFFFFFFu, mx0, 2));
        mx1 = fmaxf(mx1, __shfl_xor_sync(0xFFFFFFFFu, mx1, 1));
        mx1 = fmaxf(mx1, __shfl_xor_sync(0xFFFFFFFFu, mx1, 2));
        float mn0 = fmaxf(m0, mx0), mn1 = fmaxf(m1, mx1);
        float c0 = __expf(m0 - mn0), c1 = __expf(m1 - mn1);
        m0 = mn0; m1 = mn1;
        l0 *= c0;  l1 *= c1;
#pragma unroll
        for (int nt = 0; nt < 8; nt++) {
            ctx[nt][0] *= c0; ctx[nt][1] *= c0;
            ctx[nt][2] *= c1; ctx[nt][3] *= c1;
        }
#pragma unroll
        for (int nt = 0; nt < 8; nt++) {
            float p00 = __expf(sacc[nt][0] - mn0);
            float p01 = __expf(sacc[nt][1] - mn0);
            float p10 = __expf(sacc[nt][2] - mn1);
            float p11 = __expf(sacc[nt][3] - mn1);
            l0 += p00 + p01;
            l1 += p10 + p11;
            int c = nt * 8 + 2 * t4;
            *(float2*)(pw + g * KSTR + c)       = make_float2(to_tf32(p00), to_tf32(p01));
            *(float2*)(pw + (g + 8) * KSTR + c) = make_float2(to_tf32(p10), to_tf32(p11));
        }
        __syncwarp();

#pragma unroll
        for (int ks = 0; ks < 8; ks++) {
            int k = ks * 8;
            uint32_t af[4];
            ldmx4(af, p_lm + ks * 32);
#pragma unroll
            for (int nt = 0; nt < 8; nt++) {
                uint32_t bf[2];
                bf[0] = __float_as_uint(Vs[(k + t4) * VSTR + nt * 8 + g]);
                bf[1] = __float_as_uint(Vs[(k + t4 + 4) * VSTR + nt * 8 + g]);
                mma_tf32(ctx[nt], af, bf);
            }
        }
        __syncwarp();
    }

    l0 += __shfl_xor_sync(0xFFFFFFFFu, l0, 1);
    l0 += __shfl_xor_sync(0xFFFFFFFFu, l0, 2);
    l1 += __shfl_xor_sync(0xFFFFFFFFu, l1, 1);
    l1 += __shfl_xor_sync(0xFFFFFFFFu, l1, 2);
    float inv0 = 1.0f / l0, inv1 = 1.0f / l1;
    int s0 = q0 + wid * 16 + g;
    int b  = bh >> 4;
    int h  = bh & 15;
    float* o0 = g_ctx + ((size_t)(s0 * B_ + b) * D_ + h * HD_);
    float* o1 = g_ctx + ((size_t)((s0 + 8) * B_ + b) * D_ + h * HD_);
#pragma unroll
    for (int nt = 0; nt < 8; nt++) {
        int c = nt * 8 + 2 * t4;
        *(float2*)(o0 + c) = make_float2(to_tf32(ctx[nt][0] * inv0), to_tf32(ctx[nt][1] * inv0));
        *(float2*)(o1 + c) = make_float2(to_tf32(ctx[nt][2] * inv1), to_tf32(ctx[nt][3] * inv1));
    }
}

// ---------------- launch ----------------
extern "C" void kernel_launch(void* const* d_in, const int* in_sizes, int n_in,
                              void* d_out, int out_size)
{
    const float* src       = (const float*)d_in[0];
    const float* pos       = (const float*)d_in[1];
    const float* in_proj_w = (const float*)d_in[2];
    const float* alpha_in  = (const float*)d_in[3];
    const float* out_projw = (const float*)d_in[4];
    const float* alpha_out = (const float*)d_in[5];
    const float* w1        = (const float*)d_in[6];
    const float* b1        = (const float*)d_in[7];
    const float* alpha1    = (const float*)d_in[8];
    const float* w2        = (const float*)d_in[9];
    const float* b2        = (const float*)d_in[10];
    const float* alpha2    = (const float*)d_in[11];
    const float* ln1_g     = (const float*)d_in[12];
    const float* ln1_b     = (const float*)d_in[13];
    const float* ln2_g     = (const float*)d_in[14];
    const float* ln2_b     = (const float*)d_in[15];
    float* out = (float*)d_out;

    float *p_src2, *p_qk, *p_ctx, *p_res1, *p_src2b, *p_h, *p_al;
    cudaGetSymbolAddress((void**)&p_src2,  g_src2);
    cudaGetSymbolAddress((void**)&p_qk,    g_qk);
    cudaGetSymbolAddress((void**)&p_ctx,   g_ctx);
    cudaGetSymbolAddress((void**)&p_res1,  g_res1);
    cudaGetSymbolAddress((void**)&p_src2b, g_src2b);
    cudaGetSymbolAddress((void**)&p_h,     g_h);
    cudaGetSymbolAddress((void**)&p_al,    g_alphas);
    float *p_wi, *p_wo, *p_w1, *p_w2;
    cudaGetSymbolAddress((void**)&p_wi,    g_wi);
    cudaGetSymbolAddress((void**)&p_wo,    g_wo);
    cudaGetSymbolAddress((void**)&p_w1,    g_w1);
    cudaGetSymbolAddress((void**)&p_w2,    g_w2);

    cudaFuncSetAttribute(mma_gemm<0>, cudaFuncAttributeMaxDynamicSharedMemorySize, SM_TOTAL);
    cudaFuncSetAttribute(mma_gemm<1>, cudaFuncAttributeMaxDynamicSharedMemorySize, SM_TOTAL);
    cudaFuncSetAttribute(mma_gemm<2>, cudaFuncAttributeMaxDynamicSharedMemorySize, SM_TOTAL);
    cudaFuncSetAttribute(mma_gemm<3>, cudaFuncAttributeMaxDynamicSharedMemorySize, SM_TOTAL);
    cudaFuncSetAttribute(attn_mma_kernel, cudaFuncAttributeMaxDynamicSharedMemorySize, ASM_TOTAL);

    // quantize all 4 weight matrices in one launch (float4)
    {
        int n4 = (NWI + NWO + NW1 + NW2) / 4;
        quant_all_kernel<<<(n4 + 255) / 256, 256>>>(in_proj_w, alpha_in, out_projw, alpha_out,
                                                    w1, alpha1, w2, alpha2);
    }

    // LN1 -> src2 (tf32), qk = src2 + pos (tf32)
    ln_kernel<<<NTOK, 256>>>(src, pos, ln1_g, ln1_b, p_src2, p_qk);

    // QKV projection, scattered to [B,H,S,HD] (tf32-rounded)
    mma_gemm<0><<<dim3(3 * D_ / 128, NTOK / 128), 256, SM_TOTAL>>>(
        p_qk, p_src2, p_wi, nullptr, nullptr, nullptr, D_, 3 * D_, p_al + 0);

    // attention (mma.sync tf32 flash)
    attn_mma_kernel<<<dim3(S_ / 128, B_ * H_), 256, ASM_TOTAL>>>();

    // out_proj + residual(src) -> res1
    mma_gemm<1><<<dim3(D_ / 128, NTOK / 128), 256, SM_TOTAL>>>(
        p_ctx, nullptr, p_wo, nullptr, src, p_res1, D_, D_, p_al + 1);

    // LN2 -> src2b (tf32)
    ln_kernel<<<NTOK, 256>>>(p_res1, nullptr, ln2_g, ln2_b, p_src2b, nullptr);

    // FFN1: relu(src2b @ w1^T + b1) -> h (tf32)
    mma_gemm<2><<<dim3(DFF_ / 128, NTOK / 128), 256, SM_TOTAL>>>(
        p_src2b, nullptr, p_w1, b1, nullptr, p_h, D_, DFF_, p_al + 2);

    // FFN2: res1 + h @ w2^T + b2 -> out
    mma_gemm<3><<<dim3(D_ / 128, NTOK / 128), 256, SM_TOTAL>>>(
        p_h, nullptr, p_w2, b2, p_res1, out, DFF_, D_, p_al + 3);
}

// round 10
// speedup vs baseline: 1.6818x; 1.6818x over previous
#include <cuda_runtime.h>
#include <cuda_fp16.h>
#include <cmath>
#include <cstdint>

#define S_   1024
#define B_   4
#define D_   1024
#define H_   16
#define HD_  64
#define DFF_ 4096
#define NTOK 4096   // S_*B_

// ---------------- device-global scratch (no allocations allowed) ----------------
__device__ __half g_src2 [NTOK * D_];    // LN1(src)           (fp16)
__device__ __half g_qk   [NTOK * D_];    // LN1(src) + pos     (fp16)
__device__ float  g_q    [NTOK * D_];    // [B,H,S,HD], alpha/8 folded, tf32
__device__ float  g_k    [NTOK * D_];    // [B,H,S,HD], tf32
__device__ float  g_v    [NTOK * D_];    // [B,H,S,HD], tf32
__device__ __half g_ctx  [NTOK * D_];    // attention output, [S,B,D] (fp16)
__device__ float  g_res1 [NTOK * D_];    // src + attn_out (fp32 residual)
__device__ __half g_src2b[NTOK * D_];    // LN2(res1)          (fp16)
__device__ __half g_h    [NTOK * DFF_];  // relu(ffn1)         (fp16)
__device__ __half g_wi   [3 * D_ * D_];  // quantized in_proj_w  (exact ints)
__device__ __half g_wo   [D_ * D_];      // quantized out_proj_w (exact ints)
__device__ __half g_w1   [DFF_ * D_];    // quantized w1         (exact ints)
__device__ __half g_w2   [D_ * DFF_];    // quantized w2         (exact ints)
__device__ float  g_alphas[4];           // effective LSQ scales (in, out, w1, w2)

// ================= helpers =================
__device__ __forceinline__ uint32_t smem_u32(const void* p) {
    uint32_t a;
    asm("{ .reg .u64 t; cvta.to.shared.u64 t, %1; cvt.u32.u64 %0, t; }" : "=r"(a) : "l"(p));
    return a;
}
__device__ __forceinline__ float to_tf32(float x) {
    uint32_t r;
    asm("cvt.rna.tf32.f32 %0, %1;" : "=r"(r) : "f"(x));
    return __uint_as_float(r);
}
__device__ __forceinline__ void cp_async16(uint32_t saddr, const void* gaddr) {
    asm volatile("cp.async.cg.shared.global [%0], [%1], 16;" :: "r"(saddr), "l"(gaddr));
}
#define CP_COMMIT()  asm volatile("cp.async.commit_group;" ::: "memory")
#define CP_WAIT(n)   asm volatile("cp.async.wait_group %0;" :: "n"(n) : "memory")

// mma.sync m16n8k16 fp16 with fp32 accumulate (baseline sm_80+)
__device__ __forceinline__ void mma_f16(float* d, const uint32_t* a, const uint32_t* b) {
    asm volatile(
        "mma.sync.aligned.m16n8k16.row.col.f32.f16.f16.f32 "
        "{%0,%1,%2,%3}, {%4,%5,%6,%7}, {%8,%9}, {%0,%1,%2,%3};"
        : "+f"(d[0]), "+f"(d[1]), "+f"(d[2]), "+f"(d[3])
        : "r"(a[0]), "r"(a[1]), "r"(a[2]), "r"(a[3]), "r"(b[0]), "r"(b[1]));
}
// mma.sync m16n8k8 tf32 (attention path)
__device__ __forceinline__ void mma_tf32(float* d, const uint32_t* a, const uint32_t* b) {
    asm volatile(
        "mma.sync.aligned.m16n8k8.row.col.f32.tf32.tf32.f32 "
        "{%0,%1,%2,%3}, {%4,%5,%6,%7}, {%8,%9}, {%0,%1,%2,%3};"
        : "+f"(d[0]), "+f"(d[1]), "+f"(d[2]), "+f"(d[3])
        : "r"(a[0]), "r"(a[1]), "r"(a[2]), "r"(a[3]), "r"(b[0]), "r"(b[1]));
}
__device__ __forceinline__ void ldmx4(uint32_t* r, uint32_t addr) {
    asm volatile("ldmatrix.sync.aligned.m8n8.x4.shared.b16 {%0,%1,%2,%3}, [%4];"
        : "=r"(r[0]), "=r"(r[1]), "=r"(r[2]), "=r"(r[3]) : "r"(addr));
}

// ---------------- LSQ weight quantization: all 4 matrices, one launch ----------------
#define NWI (3 * D_ * D_)
#define NWO (D_ * D_)
#define NW1 (DFF_ * D_)
#define NW2 (D_ * DFF_)
__global__ void quant_all_kernel(
    const float* __restrict__ wi, const float* __restrict__ ai,
    const float* __restrict__ wo, const float* __restrict__ ao,
    const float* __restrict__ w1, const float* __restrict__ a1,
    const float* __restrict__ w2, const float* __restrict__ a2)
{
    int i = blockIdx.x * blockDim.x + threadIdx.x;     // float4 index
    const float* w; const float* alp; __half* out; float gg; int slot; int li;
    if (i < NWI / 4) {
        w = wi; alp = ai; out = g_wi; li = i; slot = 0;
        gg = 2.1308894e-4f;
    } else if (i < (NWI + NWO) / 4) {
        w = wo; alp = ao; out = g_wo; li = i - NWI / 4; slot = 1;
        gg = 3.6908489e-4f;
    } else if (i < (NWI + NWO + NW1) / 4) {
        w = w1; alp = a1; out = g_w1; li = i - (NWI + NWO) / 4; slot = 2;
        gg = 1.8454244e-4f;
    } else if (i < (NWI + NWO + NW1 + NW2) / 4) {
        w = w2; alp = a2; out = g_w2; li = i - (NWI + NWO + NW1) / 4; slot = 3;
        gg = 1.8454244e-4f;
    } else return;
    float al = alp[0];
    float ag = al * gg;
    float a  = ag + (al - ag);
    float inv = 1.0f / a;
    float4 v = ((const float4*)w)[li];
    float qx = rintf(fminf(fmaxf(v.x * inv, -8.0f), 7.0f));
    float qy = rintf(fminf(fmaxf(v.y * inv, -8.0f), 7.0f));
    float qz = rintf(fminf(fmaxf(v.z * inv, -8.0f), 7.0f));
    float qw = rintf(fminf(fmaxf(v.w * inv, -8.0f), 7.0f));
    __half2 h01 = __floats2half2_rn(qx, qy);
    __half2 h23 = __floats2half2_rn(qz, qw);
    uint2 u;
    u.x = *(const uint32_t*)&h01;
    u.y = *(const uint32_t*)&h23;
    ((uint2*)out)[li] = u;
    if (li == 0) g_alphas[slot] = a;
}

// ---------------- LayerNorm (one block per row of 1024); fp16 outputs ----------------
__global__ __launch_bounds__(256) void ln_kernel(
    const float* __restrict__ x, const float* __restrict__ pos,
    const float* __restrict__ gamma, const float* __restrict__ beta,
    __half* __restrict__ y, __half* __restrict__ yp)
{
    int row = blockIdx.x;
    int t   = threadIdx.x;
    const float4* xr = (const float4*)(x + (size_t)row * D_);
    float4 v = xr[t];
    float s  = v.x + v.y + v.z + v.w;
    float ss = v.x * v.x + v.y * v.y + v.z * v.z + v.w * v.w;
#pragma unroll
    for (int o = 16; o > 0; o >>= 1) {
        s  += __shfl_xor_sync(0xFFFFFFFFu, s,  o);
        ss += __shfl_xor_sync(0xFFFFFFFFu, ss, o);
    }
    __shared__ float ws[8], wss[8], fin[2];
    int w = t >> 5;
    if ((t & 31) == 0) { ws[w] = s; wss[w] = ss; }
    __syncthreads();
    if (t == 0) {
        float a = 0.f, b = 0.f;
#pragma unroll
        for (int i = 0; i < 8; i++) { a += ws[i]; b += wss[i]; }
        float m   = a * (1.0f / D_);
        float var = b * (1.0f / D_) - m * m;
        fin[0] = m;
        fin[1] = rsqrtf(var + 1e-5f);
    }
    __syncthreads();
    float m = fin[0], r = fin[1];
    float4 g4 = ((const float4*)gamma)[t];
    float4 b4 = ((const float4*)beta)[t];
    float4 o;
    o.x = (v.x - m) * r * g4.x + b4.x;
    o.y = (v.y - m) * r * g4.y + b4.y;
    o.z = (v.z - m) * r * g4.z + b4.z;
    o.w = (v.w - m) * r * g4.w + b4.w;
    {
        __half2 h01 = __floats2half2_rn(o.x, o.y);
        __half2 h23 = __floats2half2_rn(o.z, o.w);
        uint2 u; u.x = *(const uint32_t*)&h01; u.y = *(const uint32_t*)&h23;
        ((uint2*)(y + (size_t)row * D_))[t] = u;
    }
    if (yp) {
        float4 p = ((const float4*)(pos + (size_t)row * D_))[t];
        __half2 h01 = __floats2half2_rn(o.x + p.x, o.y + p.y);
        __half2 h23 = __floats2half2_rn(o.z + p.z, o.w + p.w);
        uint2 u; u.x = *(const uint32_t*)&h01; u.y = *(const uint32_t*)&h23;
        ((uint2*)(yp + (size_t)row * D_))[t] = u;
    }
}

// =============== fp16 mma.sync GEMM: C = scale * (A[M,K] @ W[Nn,K]^T) + epi ===============
// CTA tile 128x128, BK=64 halfs, 8 warps (2x4), warp tile 64x32, 3-stage single-barrier pipeline.
// Smem row = 64 halfs (128B) padded to 144B; 36r mod 32 = {0,4,..,28} -> ldmatrix conflict-free.
#define SROW_B  144                      // bytes per smem row
#define ATILE   (128 * SROW_B)           // 18432 B per tile
#define STAGE   (2 * ATILE)              // 36864 B
#define NSTAGE  3
#define SM_TOTAL (NSTAGE * STAGE)        // 110592 B

template <int EPI>
__global__ __launch_bounds__(256) void mma_gemm(
    const __half* __restrict__ A, const __half* __restrict__ A2,
    const __half* __restrict__ W, const float* __restrict__ bias,
    const float* __restrict__ resid, void* __restrict__ Cv,
    int K, int Nn, const float* __restrict__ alpha)
{
    extern __shared__ char smem[];
    uint32_t sb = smem_u32(smem);
    int tid = threadIdx.x;
    int wid = tid >> 5;
    int lane = tid & 31;
    int g  = lane >> 2;
    int t4 = lane & 3;
    int q3 = lane >> 3;
    int rin = lane & 7;
    int warp_m = wid >> 2;
    int warp_n = wid & 3;

    int brow = blockIdx.y * 128;
    int bcol = blockIdx.x * 128;
    const __half* Ain = (EPI == 0 && bcol >= 2 * D_) ? A2 : A;

    // cp.async mapping: thread t -> tile row t>>1, 64B half (t&1), 4x16B each
    int lrow = tid >> 1;
    int lhalf = tid & 1;
    const __half* agp = Ain + (size_t)(brow + lrow) * K + lhalf * 32;
    const __half* wgp = W   + (size_t)(bcol + lrow) * K + lhalf * 32;
    uint32_t sa = sb + lrow * SROW_B + lhalf * 64;
    uint32_t sw = sa + ATILE;

    // ldmatrix per-lane bases
    // A m16k16 frags: row + (q3&1)*8, kcol + (q3>>1)*16B
    uint32_t a_lm = sb + (warp_m * 64 + (q3 & 1) * 8 + rin) * SROW_B + (q3 >> 1) * 16;
    // B n16k16 (two n8k16 frags): row n + (q3>>1)*8, kcol + (q3&1)*16B
    uint32_t b_lm = sb + ATILE + (warp_n * 32 + (q3 >> 1) * 8 + rin) * SROW_B + (q3 & 1) * 16;

    float acc[4][4][4];
#pragma unroll
    for (int i = 0; i < 4; i++)
#pragma unroll
        for (int j = 0; j < 4; j++)
#pragma unroll
            for (int e = 0; e < 4; e++) acc[i][j][e] = 0.f;

    const int nch = K / 64;

#define ISSUE(c, s) do {                                              \
        int k0_ = (c) * 64;                                           \
        uint32_t so_ = (uint32_t)(s) * STAGE;                         \
        _Pragma("unroll")                                             \
        for (int q_ = 0; q_ < 4; q_++) {                              \
            cp_async16(sa + so_ + q_ * 16, agp + k0_ + q_ * 8);       \
            cp_async16(sw + so_ + q_ * 16, wgp + k0_ + q_ * 8);       \
        }                                                             \
    } while (0)

    ISSUE(0, 0); CP_COMMIT();
    ISSUE(1, 1); CP_COMMIT();
    CP_WAIT(1);
    __syncthreads();

    for (int i = 0; i < nch; i++) {
        if (i + 2 < nch) ISSUE(i + 2, (i + 2) % NSTAGE);
        CP_COMMIT();

        int s = i % NSTAGE;
        uint32_t ab = a_lm + (uint32_t)s * STAGE;
        uint32_t bb = b_lm + (uint32_t)s * STAGE;
#pragma unroll
        for (int ks = 0; ks < 4; ks++) {         // 4 k16 steps per 64-half chunk
            uint32_t af[4][4], bq[2][4];
#pragma unroll
            for (int mt = 0; mt < 4; mt++)
                ldmx4(af[mt], ab + mt * (16 * SROW_B) + ks * 32);
#pragma unroll
            for (int pr = 0; pr < 2; pr++)
                ldmx4(bq[pr], bb + pr * (16 * SROW_B) + ks * 32);
#pragma unroll
            for (int mt = 0; mt < 4; mt++) {
                mma_f16(acc[mt][0], af[mt], &bq[0][0]);
                mma_f16(acc[mt][1], af[mt], &bq[0][2]);
                mma_f16(acc[mt][2], af[mt], &bq[1][0]);
                mma_f16(acc[mt][3], af[mt], &bq[1][2]);
            }
        }

        CP_WAIT(1);
        __syncthreads();
    }
#undef ISSUE

    float scale = __ldg(alpha);
#pragma unroll
    for (int mt = 0; mt < 4; mt++) {
        int r0 = brow + warp_m * 64 + mt * 16 + g;
#pragma unroll
        for (int half = 0; half < 2; half++) {
            int rr = r0 + half * 8;
#pragma unroll
            for (int nt = 0; nt < 4; nt++) {
                int c = bcol + warp_n * 32 + nt * 8 + t4 * 2;
                float v0 = acc[mt][nt][half * 2 + 0];
                float v1 = acc[mt][nt][half * 2 + 1];
                if (EPI == 0) {
                    int region = bcol >> 10;
                    float sc = (region == 0) ? scale * 0.125f : scale;
                    float* dst0 = (region == 0) ? g_q : (region == 1) ? g_k : g_v;
                    int s  = rr >> 2;
                    int bb = rr & 3;
                    int cd = c & 1023;
                    int h  = cd >> 6, d = cd & 63;
                    float2 o = make_float2(to_tf32(v0 * sc), to_tf32(v1 * sc));
                    *(float2*)(dst0 + (((size_t)bb * H_ + h) * S_ + s) * HD_ + d) = o;
                } else if (EPI == 2) {
                    // relu + bias -> fp16 h
                    float2 bb = *(const float2*)(bias + c);
                    v0 = fmaxf(v0 * scale + bb.x, 0.f);
                    v1 = fmaxf(v1 * scale + bb.y, 0.f);
                    *(__half2*)((__half*)Cv + (size_t)rr * Nn + c) = __floats2half2_rn(v0, v1);
                } else {
                    float* crow = (float*)Cv + (size_t)rr * Nn + c;
                    v0 *= scale; v1 *= scale;
                    if (EPI == 3) {
                        float2 bb = *(const float2*)(bias + c);
                        float2 rv = *(const float2*)(resid + (size_t)rr * Nn + c);
                        v0 += bb.x + rv.x; v1 += bb.y + rv.y;
                    }
                    if (EPI == 1) {
                        float2 rv = *(const float2*)(resid + (size_t)rr * Nn + c);
                        v0 += rv.x; v1 += rv.y;
                    }
                    *(float2*)crow = make_float2(v0, v1);
                }
            }
        }
    }
}

// =============== Flash attention on mma.sync tf32 + ldmatrix (unchanged math) ===============
#define KSTR 68
#define VSTR 72
#define ASM_K 0
#define ASM_V (64 * KSTR)
#define ASM_P (64 * KSTR + 64 * VSTR)
#define ASM_TOTAL ((64 * KSTR + 64 * VSTR + 128 * KSTR) * 4)

__global__ __launch_bounds__(256) void attn_mma_kernel()
{
    extern __shared__ float sm[];
    float* Ks = sm + ASM_K;
    float* Vs = sm + ASM_V;
    float* Ps = sm + ASM_P;
    uint32_t sb = smem_u32(sm);

    int tid  = threadIdx.x;
    int wid  = tid >> 5;
    int lane = tid & 31;
    int g    = lane >> 2;
    int t4   = lane & 3;
    int q3   = lane >> 3;
    int rin  = lane & 7;
    int bh   = blockIdx.y;
    int q0   = blockIdx.x * 128;

    const float* Qb = g_q + ((size_t)bh * S_ + q0 + wid * 16) * HD_;
    uint32_t qf[8][4];
#pragma unroll
    for (int ks = 0; ks < 8; ks++) {
        qf[ks][0] = __float_as_uint(Qb[g * HD_ + ks * 8 + t4]);
        qf[ks][1] = __float_as_uint(Qb[(g + 8) * HD_ + ks * 8 + t4]);
        qf[ks][2] = __float_as_uint(Qb[g * HD_ + ks * 8 + t4 + 4]);
        qf[ks][3] = __float_as_uint(Qb[(g + 8) * HD_ + ks * 8 + t4 + 4]);
    }

    float ctx[8][4];
#pragma unroll
    for (int nt = 0; nt < 8; nt++)
#pragma unroll
        for (int e = 0; e < 4; e++) ctx[nt][e] = 0.f;
    float m0 = -1e30f, m1 = -1e30f, l0 = 0.f, l1 = 0.f;

    const float* kbase = g_k + (size_t)bh * S_ * HD_;
    const float* vbase = g_v + (size_t)bh * S_ * HD_;
    float* pw = Ps + (wid * 16) * KSTR;

    uint32_t k_lm = sb + (ASM_K + ((q3 >> 1) * 8 + rin) * KSTR) * 4 + (q3 & 1) * 16;
    uint32_t p_lm = sb + (ASM_P + (wid * 16 + (q3 & 1) * 8 + rin) * KSTR) * 4 + (q3 >> 1) * 16;

    for (int kt = 0; kt < 16; kt++) {
        __syncthreads();
#pragma unroll
        for (int i = 0; i < 4; i++) {
            int idx = i * 256 + tid;
            int r = idx >> 4, c4 = (idx & 15) * 4;
            *(float4*)(Ks + r * KSTR + c4) =
                *(const float4*)(kbase + (size_t)(kt * 64 + r) * HD_ + c4);
            *(float4*)(Vs + r * VSTR + c4) =
                *(const float4*)(vbase + (size_t)(kt * 64 + r) * HD_ + c4);
        }
        __syncthreads();

        float sacc[8][4];
#pragma unroll
        for (int nt = 0; nt < 8; nt++)
#pragma unroll
            for (int e = 0; e < 4; e++) sacc[nt][e] = 0.f;
#pragma unroll
        for (int ks = 0; ks < 8; ks++) {
#pragma unroll
            for (int pr = 0; pr < 4; pr++) {
                uint32_t kq[4];
                ldmx4(kq, k_lm + pr * (16 * KSTR * 4) + ks * 32);
                mma_tf32(sacc[pr * 2 + 0], qf[ks], &kq[0]);
                mma_tf32(sacc[pr * 2 + 1], qf[ks], &kq[2]);
            }
        }

        float mx0 = -1e30f, mx1 = -1e30f;
#pragma unroll
        for (int nt = 0; nt < 8; nt++) {
            mx0 = fmaxf(mx0, fmaxf(sacc[nt][0], sacc[nt][1]));
            mx1 = fmaxf(mx1, fmaxf(sacc[nt][2], sacc[nt][3]));
        }
        mx0 = fmaxf(mx0, __shfl_xor_sync(0xFFFFFFFFu, mx0, 1));
        mx0 = fmaxf(mx0, __shfl_xor_sync(0xFFFFFFFFu, mx0, 2));
        mx1 = fmaxf(mx1, __shfl_xor_sync(0xFFFFFFFFu, mx1, 1));
        mx1 = fmaxf(mx1, __shfl_xor_sync(0xFFFFFFFFu, mx1, 2));
        float mn0 = fmaxf(m0, mx0), mn1 = fmaxf(m1, mx1);
        float c0 = __expf(m0 - mn0), c1 = __expf(m1 - mn1);
        m0 = mn0; m1 = mn1;
        l0 *= c0;  l1 *= c1;
#pragma unroll
        for (int nt = 0; nt < 8; nt++) {
            ctx[nt][0] *= c0; ctx[nt][1] *= c0;
            ctx[nt][2] *= c1; ctx[nt][3] *= c1;
        }
#pragma unroll
        for (int nt = 0; nt < 8; nt++) {
            float p00 = __expf(sacc[nt][0] - mn0);
            float p01 = __expf(sacc[nt][1] - mn0);
            float p10 = __expf(sacc[nt][2] - mn1);
            float p11 = __expf(sacc[nt][3] - mn1);
            l0 += p00 + p01;
            l1 += p10 + p11;
            int c = nt * 8 + 2 * t4;
            *(float2*)(pw + g * KSTR + c)       = make_float2(to_tf32(p00), to_tf32(p01));
            *(float2*)(pw + (g + 8) * KSTR + c) = make_float2(to_tf32(p10), to_tf32(p11));
        }
        __syncwarp();

#pragma unroll
        for (int ks = 0; ks < 8; ks++) {
            int k = ks * 8;
            uint32_t af[4];
            ldmx4(af, p_lm + ks * 32);
#pragma unroll
            for (int nt = 0; nt < 8; nt++) {
                uint32_t bf[2];
                bf[0] = __float_as_uint(Vs[(k + t4) * VSTR + nt * 8 + g]);
                bf[1] = __float_as_uint(Vs[(k + t4 + 4) * VSTR + nt * 8 + g]);
                mma_tf32(ctx[nt], af, bf);
            }
        }
        __syncwarp();
    }

    l0 += __shfl_xor_sync(0xFFFFFFFFu, l0, 1);
    l0 += __shfl_xor_sync(0xFFFFFFFFu, l0, 2);
    l1 += __shfl_xor_sync(0xFFFFFFFFu, l1, 1);
    l1 += __shfl_xor_sync(0xFFFFFFFFu, l1, 2);
    float inv0 = 1.0f / l0, inv1 = 1.0f / l1;
    int s0 = q0 + wid * 16 + g;
    int b  = bh >> 4;
    int h  = bh & 15;
    __half* o0 = g_ctx + ((size_t)(s0 * B_ + b) * D_ + h * HD_);
    __half* o1 = g_ctx + ((size_t)((s0 + 8) * B_ + b) * D_ + h * HD_);
#pragma unroll
    for (int nt = 0; nt < 8; nt++) {
        int c = nt * 8 + 2 * t4;
        *(__half2*)(o0 + c) = __floats2half2_rn(ctx[nt][0] * inv0, ctx[nt][1] * inv0);
        *(__half2*)(o1 + c) = __floats2half2_rn(ctx[nt][2] * inv1, ctx[nt][3] * inv1);
    }
}

// ---------------- launch ----------------
extern "C" void kernel_launch(void* const* d_in, const int* in_sizes, int n_in,
                              void* d_out, int out_size)
{
    const float* src       = (const float*)d_in[0];
    const float* pos       = (const float*)d_in[1];
    const float* in_proj_w = (const float*)d_in[2];
    const float* alpha_in  = (const float*)d_in[3];
    const float* out_projw = (const float*)d_in[4];
    const float* alpha_out = (const float*)d_in[5];
    const float* w1        = (const float*)d_in[6];
    const float* b1        = (const float*)d_in[7];
    const float* alpha1    = (const float*)d_in[8];
    const float* w2        = (const float*)d_in[9];
    const float* b2        = (const float*)d_in[10];
    const float* alpha2    = (const float*)d_in[11];
    const float* ln1_g     = (const float*)d_in[12];
    const float* ln1_b     = (const float*)d_in[13];
    const float* ln2_g     = (const float*)d_in[14];
    const float* ln2_b     = (const float*)d_in[15];
    float* out = (float*)d_out;

    __half *p_src2, *p_qk, *p_ctx, *p_src2b, *p_h, *p_wi, *p_wo, *p_w1, *p_w2;
    float  *p_res1, *p_al;
    cudaGetSymbolAddress((void**)&p_src2,  g_src2);
    cudaGetSymbolAddress((void**)&p_qk,    g_qk);
    cudaGetSymbolAddress((void**)&p_ctx,   g_ctx);
    cudaGetSymbolAddress((void**)&p_res1,  g_res1);
    cudaGetSymbolAddress((void**)&p_src2b, g_src2b);
    cudaGetSymbolAddress((void**)&p_h,     g_h);
    cudaGetSymbolAddress((void**)&p_al,    g_alphas);
    cudaGetSymbolAddress((void**)&p_wi,    g_wi);
    cudaGetSymbolAddress((void**)&p_wo,    g_wo);
    cudaGetSymbolAddress((void**)&p_w1,    g_w1);
    cudaGetSymbolAddress((void**)&p_w2,    g_w2);

    cudaFuncSetAttribute(mma_gemm<0>, cudaFuncAttributeMaxDynamicSharedMemorySize, SM_TOTAL);
    cudaFuncSetAttribute(mma_gemm<1>, cudaFuncAttributeMaxDynamicSharedMemorySize, SM_TOTAL);
    cudaFuncSetAttribute(mma_gemm<2>, cudaFuncAttributeMaxDynamicSharedMemorySize, SM_TOTAL);
    cudaFuncSetAttribute(mma_gemm<3>, cudaFuncAttributeMaxDynamicSharedMemorySize, SM_TOTAL);
    cudaFuncSetAttribute(attn_mma_kernel, cudaFuncAttributeMaxDynamicSharedMemorySize, ASM_TOTAL);

    // quantize all 4 weight matrices -> fp16 integers (exact)
    {
        int n4 = (NWI + NWO + NW1 + NW2) / 4;
        quant_all_kernel<<<(n4 + 255) / 256, 256>>>(in_proj_w, alpha_in, out_projw, alpha_out,
                                                    w1, alpha1, w2, alpha2);
    }

    // LN1 -> src2 (fp16), qk = src2 + pos (fp16)
    ln_kernel<<<NTOK, 256>>>(src, pos, ln1_g, ln1_b, p_src2, p_qk);

    // QKV projection (fp16 mma), scattered to [B,H,S,HD] fp32/tf32
    mma_gemm<0><<<dim3(3 * D_ / 128, NTOK / 128), 256, SM_TOTAL>>>(
        p_qk, p_src2, p_wi, nullptr, nullptr, nullptr, D_, 3 * D_, p_al + 0);

    // attention (tf32 flash) -> g_ctx fp16
    attn_mma_kernel<<<dim3(S_ / 128, B_ * H_), 256, ASM_TOTAL>>>();

    // out_proj + residual(src) -> res1 (fp32)
    mma_gemm<1><<<dim3(D_ / 128, NTOK / 128), 256, SM_TOTAL>>>(
        p_ctx, nullptr, p_wo, nullptr, src, p_res1, D_, D_, p_al + 1);

    // LN2 -> src2b (fp16)
    ln_kernel<<<NTOK, 256>>>(p_res1, nullptr, ln2_g, ln2_b, p_src2b, nullptr);

    // FFN1: relu(src2b @ w1^T + b1) -> h (fp16)
    mma_gemm<2><<<dim3(DFF_ / 128, NTOK / 128), 256, SM_TOTAL>>>(
        p_src2b, nullptr, p_w1, b1, nullptr, p_h, D_, DFF_, p_al + 2);

    // FFN2: res1 + h @ w2^T + b2 -> out (fp32)
    mma_gemm<3><<<dim3(D_ / 128, NTOK / 128), 256, SM_TOTAL>>>(
        p_h, nullptr, p_w2, b2, p_res1, out, DFF_, D_, p_al + 3);
}

// round 11
// speedup vs baseline: 1.6823x; 1.0003x over previous
#include <cuda_runtime.h>
#include <cuda_fp16.h>
#include <cmath>
#include <cstdint>

#define S_   1024
#define B_   4
#define D_   1024
#define H_   16
#define HD_  64
#define DFF_ 4096
#define NTOK 4096   // S_*B_

// ---------------- device-global scratch (no allocations allowed) ----------------
__device__ __half g_src2 [NTOK * D_];    // LN1(src)           (fp16)
__device__ __half g_qk   [NTOK * D_];    // LN1(src) + pos     (fp16)
__device__ float  g_q    [NTOK * D_];    // [B,H,S,HD], alpha/8 folded, tf32
__device__ float  g_k    [NTOK * D_];    // [B,H,S,HD], tf32
__device__ float  g_v    [NTOK * D_];    // [B,H,S,HD], tf32
__device__ __half g_ctx  [NTOK * D_];    // attention output, [S,B,D] (fp16)
__device__ float  g_res1 [NTOK * D_];    // src + attn_out (fp32 residual)
__device__ __half g_src2b[NTOK * D_];    // LN2(res1)          (fp16)
__device__ __half g_h    [NTOK * DFF_];  // relu(ffn1)         (fp16)
__device__ __half g_wi   [3 * D_ * D_];  // quantized in_proj_w  (exact ints)
__device__ __half g_wo   [D_ * D_];      // quantized out_proj_w (exact ints)
__device__ __half g_w1   [DFF_ * D_];    // quantized w1         (exact ints)
__device__ __half g_w2   [D_ * DFF_];    // quantized w2         (exact ints)
__device__ float  g_alphas[4];           // effective LSQ scales (in, out, w1, w2)

// ================= helpers =================
__device__ __forceinline__ uint32_t smem_u32(const void* p) {
    uint32_t a;
    asm("{ .reg .u64 t; cvta.to.shared.u64 t, %1; cvt.u32.u64 %0, t; }" : "=r"(a) : "l"(p));
    return a;
}
__device__ __forceinline__ float to_tf32(float x) {
    uint32_t r;
    asm("cvt.rna.tf32.f32 %0, %1;" : "=r"(r) : "f"(x));
    return __uint_as_float(r);
}
__device__ __forceinline__ void cp_async16(uint32_t saddr, const void* gaddr) {
    asm volatile("cp.async.cg.shared.global [%0], [%1], 16;" :: "r"(saddr), "l"(gaddr));
}
#define CP_COMMIT()  asm volatile("cp.async.commit_group;" ::: "memory")
#define CP_WAIT(n)   asm volatile("cp.async.wait_group %0;" :: "n"(n) : "memory")

// mma.sync m16n8k16 fp16 with fp32 accumulate (baseline sm_80+)
__device__ __forceinline__ void mma_f16(float* d, const uint32_t* a, const uint32_t* b) {
    asm volatile(
        "mma.sync.aligned.m16n8k16.row.col.f32.f16.f16.f32 "
        "{%0,%1,%2,%3}, {%4,%5,%6,%7}, {%8,%9}, {%0,%1,%2,%3};"
        : "+f"(d[0]), "+f"(d[1]), "+f"(d[2]), "+f"(d[3])
        : "r"(a[0]), "r"(a[1]), "r"(a[2]), "r"(a[3]), "r"(b[0]), "r"(b[1]));
}
// mma.sync m16n8k8 tf32 (attention path)
__device__ __forceinline__ void mma_tf32(float* d, const uint32_t* a, const uint32_t* b) {
    asm volatile(
        "mma.sync.aligned.m16n8k8.row.col.f32.tf32.tf32.f32 "
        "{%0,%1,%2,%3}, {%4,%5,%6,%7}, {%8,%9}, {%0,%1,%2,%3};"
        : "+f"(d[0]), "+f"(d[1]), "+f"(d[2]), "+f"(d[3])
        : "r"(a[0]), "r"(a[1]), "r"(a[2]), "r"(a[3]), "r"(b[0]), "r"(b[1]));
}
__device__ __forceinline__ void ldmx4(uint32_t* r, uint32_t addr) {
    asm volatile("ldmatrix.sync.aligned.m8n8.x4.shared.b16 {%0,%1,%2,%3}, [%4];"
        : "=r"(r[0]), "=r"(r[1]), "=r"(r[2]), "=r"(r[3]) : "r"(addr));
}

// ---------------- LSQ weight quantization: all 4 matrices, one launch ----------------
#define NWI (3 * D_ * D_)
#define NWO (D_ * D_)
#define NW1 (DFF_ * D_)
#define NW2 (D_ * DFF_)
__global__ void quant_all_kernel(
    const float* __restrict__ wi, const float* __restrict__ ai,
    const float* __restrict__ wo, const float* __restrict__ ao,
    const float* __restrict__ w1, const float* __restrict__ a1,
    const float* __restrict__ w2, const float* __restrict__ a2)
{
    int i = blockIdx.x * blockDim.x + threadIdx.x;     // float4 index
    const float* w; const float* alp; __half* out; float gg; int slot; int li;
    if (i < NWI / 4) {
        w = wi; alp = ai; out = g_wi; li = i; slot = 0;
        gg = 2.1308894e-4f;
    } else if (i < (NWI + NWO) / 4) {
        w = wo; alp = ao; out = g_wo; li = i - NWI / 4; slot = 1;
        gg = 3.6908489e-4f;
    } else if (i < (NWI + NWO + NW1) / 4) {
        w = w1; alp = a1; out = g_w1; li = i - (NWI + NWO) / 4; slot = 2;
        gg = 1.8454244e-4f;
    } else if (i < (NWI + NWO + NW1 + NW2) / 4) {
        w = w2; alp = a2; out = g_w2; li = i - (NWI + NWO + NW1) / 4; slot = 3;
        gg = 1.8454244e-4f;
    } else return;
    float al = alp[0];
    float ag = al * gg;
    float a  = ag + (al - ag);
    float inv = 1.0f / a;
    float4 v = ((const float4*)w)[li];
    float qx = rintf(fminf(fmaxf(v.x * inv, -8.0f), 7.0f));
    float qy = rintf(fminf(fmaxf(v.y * inv, -8.0f), 7.0f));
    float qz = rintf(fminf(fmaxf(v.z * inv, -8.0f), 7.0f));
    float qw = rintf(fminf(fmaxf(v.w * inv, -8.0f), 7.0f));
    __half2 h01 = __floats2half2_rn(qx, qy);
    __half2 h23 = __floats2half2_rn(qz, qw);
    uint2 u;
    u.x = *(const uint32_t*)&h01;
    u.y = *(const uint32_t*)&h23;
    ((uint2*)out)[li] = u;
    if (li == 0) g_alphas[slot] = a;
}

// ---------------- LayerNorm (one block per row of 1024); fp16 outputs ----------------
__global__ __launch_bounds__(256) void ln_kernel(
    const float* __restrict__ x, const float* __restrict__ pos,
    const float* __restrict__ gamma, const float* __restrict__ beta,
    __half* __restrict__ y, __half* __restrict__ yp)
{
    int row = blockIdx.x;
    int t   = threadIdx.x;
    const float4* xr = (const float4*)(x + (size_t)row * D_);
    float4 v = xr[t];
    float s  = v.x + v.y + v.z + v.w;
    float ss = v.x * v.x + v.y * v.y + v.z * v.z + v.w * v.w;
#pragma unroll
    for (int o = 16; o > 0; o >>= 1) {
        s  += __shfl_xor_sync(0xFFFFFFFFu, s,  o);
        ss += __shfl_xor_sync(0xFFFFFFFFu, ss, o);
    }
    __shared__ float ws[8], wss[8], fin[2];
    int w = t >> 5;
    if ((t & 31) == 0) { ws[w] = s; wss[w] = ss; }
    __syncthreads();
    if (t == 0) {
        float a = 0.f, b = 0.f;
#pragma unroll
        for (int i = 0; i < 8; i++) { a += ws[i]; b += wss[i]; }
        float m   = a * (1.0f / D_);
        float var = b * (1.0f / D_) - m * m;
        fin[0] = m;
        fin[1] = rsqrtf(var + 1e-5f);
    }
    __syncthreads();
    float m = fin[0], r = fin[1];
    float4 g4 = ((const float4*)gamma)[t];
    float4 b4 = ((const float4*)beta)[t];
    float4 o;
    o.x = (v.x - m) * r * g4.x + b4.x;
    o.y = (v.y - m) * r * g4.y + b4.y;
    o.z = (v.z - m) * r * g4.z + b4.z;
    o.w = (v.w - m) * r * g4.w + b4.w;
    {
        __half2 h01 = __floats2half2_rn(o.x, o.y);
        __half2 h23 = __floats2half2_rn(o.z, o.w);
        uint2 u; u.x = *(const uint32_t*)&h01; u.y = *(const uint32_t*)&h23;
        ((uint2*)(y + (size_t)row * D_))[t] = u;
    }
    if (yp) {
        float4 p = ((const float4*)(pos + (size_t)row * D_))[t];
        __half2 h01 = __floats2half2_rn(o.x + p.x, o.y + p.y);
        __half2 h23 = __floats2half2_rn(o.z + p.z, o.w + p.w);
        uint2 u; u.x = *(const uint32_t*)&h01; u.y = *(const uint32_t*)&h23;
        ((uint2*)(yp + (size_t)row * D_))[t] = u;
    }
}

// =============== fp16 mma.sync GEMM: C = scale * (A[M,K] @ W[Nn,K]^T) + epi ===============
// CTA tile 128x128, BK=64 halfs, 8 warps (2x4), warp tile 64x32, 3-stage single-barrier pipeline.
// Smem row = 64 halfs (128B) padded to 144B; 36r mod 32 = {0,4,..,28} -> ldmatrix conflict-free.
#define SROW_B  144                      // bytes per smem row
#define ATILE   (128 * SROW_B)           // 18432 B per tile
#define STAGE   (2 * ATILE)              // 36864 B
#define NSTAGE  3
#define SM_TOTAL (NSTAGE * STAGE)        // 110592 B

template <int EPI>
__global__ __launch_bounds__(256) void mma_gemm(
    const __half* __restrict__ A, const __half* __restrict__ A2,
    const __half* __restrict__ W, const float* __restrict__ bias,
    const float* __restrict__ resid, void* __restrict__ Cv,
    int K, int Nn, const float* __restrict__ alpha)
{
    extern __shared__ char smem[];
    uint32_t sb = smem_u32(smem);
    int tid = threadIdx.x;
    int wid = tid >> 5;
    int lane = tid & 31;
    int g  = lane >> 2;
    int t4 = lane & 3;
    int q3 = lane >> 3;
    int rin = lane & 7;
    int warp_m = wid >> 2;
    int warp_n = wid & 3;

    int brow = blockIdx.y * 128;
    int bcol = blockIdx.x * 128;
    const __half* Ain = (EPI == 0 && bcol >= 2 * D_) ? A2 : A;

    // cp.async mapping: thread t -> tile row t>>1, 64B half (t&1), 4x16B each
    int lrow = tid >> 1;
    int lhalf = tid & 1;
    const __half* agp = Ain + (size_t)(brow + lrow) * K + lhalf * 32;
    const __half* wgp = W   + (size_t)(bcol + lrow) * K + lhalf * 32;
    uint32_t sa = sb + lrow * SROW_B + lhalf * 64;
    uint32_t sw = sa + ATILE;

    // ldmatrix per-lane bases
    // A m16k16 frags: row + (q3&1)*8, kcol + (q3>>1)*16B
    uint32_t a_lm = sb + (warp_m * 64 + (q3 & 1) * 8 + rin) * SROW_B + (q3 >> 1) * 16;
    // B n16k16 (two n8k16 frags): row n + (q3>>1)*8, kcol + (q3&1)*16B
    uint32_t b_lm = sb + ATILE + (warp_n * 32 + (q3 >> 1) * 8 + rin) * SROW_B + (q3 & 1) * 16;

    float acc[4][4][4];
#pragma unroll
    for (int i = 0; i < 4; i++)
#pragma unroll
        for (int j = 0; j < 4; j++)
#pragma unroll
            for (int e = 0; e < 4; e++) acc[i][j][e] = 0.f;

    const int nch = K / 64;

#define ISSUE(c, s) do {                                              \
        int k0_ = (c) * 64;                                           \
        uint32_t so_ = (uint32_t)(s) * STAGE;                         \
        _Pragma("unroll")                                             \
        for (int q_ = 0; q_ < 4; q_++) {                              \
            cp_async16(sa + so_ + q_ * 16, agp + k0_ + q_ * 8);       \
            cp_async16(sw + so_ + q_ * 16, wgp + k0_ + q_ * 8);       \
        }                                                             \
    } while (0)

    ISSUE(0, 0); CP_COMMIT();
    ISSUE(1, 1); CP_COMMIT();
    CP_WAIT(1);
    __syncthreads();

    for (int i = 0; i < nch; i++) {
        if (i + 2 < nch) ISSUE(i + 2, (i + 2) % NSTAGE);
        CP_COMMIT();

        int s = i % NSTAGE;
        uint32_t ab = a_lm + (uint32_t)s * STAGE;
        uint32_t bb = b_lm + (uint32_t)s * STAGE;
#pragma unroll
        for (int ks = 0; ks < 4; ks++) {         // 4 k16 steps per 64-half chunk
            uint32_t af[4][4], bq[2][4];
#pragma unroll
            for (int mt = 0; mt < 4; mt++)
                ldmx4(af[mt], ab + mt * (16 * SROW_B) + ks * 32);
#pragma unroll
            for (int pr = 0; pr < 2; pr++)
                ldmx4(bq[pr], bb + pr * (16 * SROW_B) + ks * 32);
#pragma unroll
            for (int mt = 0; mt < 4; mt++) {
                mma_f16(acc[mt][0], af[mt], &bq[0][0]);
                mma_f16(acc[mt][1], af[mt], &bq[0][2]);
                mma_f16(acc[mt][2], af[mt], &bq[1][0]);
                mma_f16(acc[mt][3], af[mt], &bq[1][2]);
            }
        }

        CP_WAIT(1);
        __syncthreads();
    }
#undef ISSUE

    float scale = __ldg(alpha);
#pragma unroll
    for (int mt = 0; mt < 4; mt++) {
        int r0 = brow + warp_m * 64 + mt * 16 + g;
#pragma unroll
        for (int half = 0; half < 2; half++) {
            int rr = r0 + half * 8;
#pragma unroll
            for (int nt = 0; nt < 4; nt++) {
                int c = bcol + warp_n * 32 + nt * 8 + t4 * 2;
                float v0 = acc[mt][nt][half * 2 + 0];
                float v1 = acc[mt][nt][half * 2 + 1];
                if (EPI == 0) {
                    int region = bcol >> 10;
                    float sc = (region == 0) ? scale * 0.125f : scale;
                    float* dst0 = (region == 0) ? g_q : (region == 1) ? g_k : g_v;
                    int s  = rr >> 2;
                    int bb = rr & 3;
                    int cd = c & 1023;
                    int h  = cd >> 6, d = cd & 63;
                    float2 o = make_float2(to_tf32(v0 * sc), to_tf32(v1 * sc));
                    *(float2*)(dst0 + (((size_t)bb * H_ + h) * S_ + s) * HD_ + d) = o;
                } else if (EPI == 2) {
                    // relu + bias -> fp16 h
                    float2 bb = *(const float2*)(bias + c);
                    v0 = fmaxf(v0 * scale + bb.x, 0.f);
                    v1 = fmaxf(v1 * scale + bb.y, 0.f);
                    *(__half2*)((__half*)Cv + (size_t)rr * Nn + c) = __floats2half2_rn(v0, v1);
                } else {
                    float* crow = (float*)Cv + (size_t)rr * Nn + c;
                    v0 *= scale; v1 *= scale;
                    if (EPI == 3) {
                        float2 bb = *(const float2*)(bias + c);
                        float2 rv = *(const float2*)(resid + (size_t)rr * Nn + c);
                        v0 += bb.x + rv.x; v1 += bb.y + rv.y;
                    }
                    if (EPI == 1) {
                        float2 rv = *(const float2*)(resid + (size_t)rr * Nn + c);
                        v0 += rv.x; v1 += rv.y;
                    }
                    *(float2*)crow = make_float2(v0, v1);
                }
            }
        }
    }
}

// =============== Flash attention on mma.sync tf32 + ldmatrix (unchanged math) ===============
#define KSTR 68
#define VSTR 72
#define ASM_K 0
#define ASM_V (64 * KSTR)
#define ASM_P (64 * KSTR + 64 * VSTR)
#define ASM_TOTAL ((64 * KSTR + 64 * VSTR + 128 * KSTR) * 4)

__global__ __launch_bounds__(256) void attn_mma_kernel()
{
    extern __shared__ float sm[];
    float* Ks = sm + ASM_K;
    float* Vs = sm + ASM_V;
    float* Ps = sm + ASM_P;
    uint32_t sb = smem_u32(sm);

    int tid  = threadIdx.x;
    int wid  = tid >> 5;
    int lane = tid & 31;
    int g    = lane >> 2;
    int t4   = lane & 3;
    int q3   = lane >> 3;
    int rin  = lane & 7;
    int bh   = blockIdx.y;
    int q0   = blockIdx.x * 128;

    const float* Qb = g_q + ((size_t)bh * S_ + q0 + wid * 16) * HD_;
    uint32_t qf[8][4];
#pragma unroll
    for (int ks = 0; ks < 8; ks++) {
        qf[ks][0] = __float_as_uint(Qb[g * HD_ + ks * 8 + t4]);
        qf[ks][1] = __float_as_uint(Qb[(g + 8) * HD_ + ks * 8 + t4]);
        qf[ks][2] = __float_as_uint(Qb[g * HD_ + ks * 8 + t4 + 4]);
        qf[ks][3] = __float_as_uint(Qb[(g + 8) * HD_ + ks * 8 + t4 + 4]);
    }

    float ctx[8][4];
#pragma unroll
    for (int nt = 0; nt < 8; nt++)
#pragma unroll
        for (int e = 0; e < 4; e++) ctx[nt][e] = 0.f;
    float m0 = -1e30f, m1 = -1e30f, l0 = 0.f, l1 = 0.f;

    const float* kbase = g_k + (size_t)bh * S_ * HD_;
    const float* vbase = g_v + (size_t)bh * S_ * HD_;
    float* pw = Ps + (wid * 16) * KSTR;

    uint32_t k_lm = sb + (ASM_K + ((q3 >> 1) * 8 + rin) * KSTR) * 4 + (q3 & 1) * 16;
    uint32_t p_lm = sb + (ASM_P + (wid * 16 + (q3 & 1) * 8 + rin) * KSTR) * 4 + (q3 >> 1) * 16;

    for (int kt = 0; kt < 16; kt++) {
        __syncthreads();
#pragma unroll
        for (int i = 0; i < 4; i++) {
            int idx = i * 256 + tid;
            int r = idx >> 4, c4 = (idx & 15) * 4;
            *(float4*)(Ks + r * KSTR + c4) =
                *(const float4*)(kbase + (size_t)(kt * 64 + r) * HD_ + c4);
            *(float4*)(Vs + r * VSTR + c4) =
                *(const float4*)(vbase + (size_t)(kt * 64 + r) * HD_ + c4);
        }
        __syncthreads();

        float sacc[8][4];
#pragma unroll
        for (int nt = 0; nt < 8; nt++)
#pragma unroll
            for (int e = 0; e < 4; e++) sacc[nt][e] = 0.f;
#pragma unroll
        for (int ks = 0; ks < 8; ks++) {
#pragma unroll
            for (int pr = 0; pr < 4; pr++) {
                uint32_t kq[4];
                ldmx4(kq, k_lm + pr * (16 * KSTR * 4) + ks * 32);
                mma_tf32(sacc[pr * 2 + 0], qf[ks], &kq[0]);
                mma_tf32(sacc[pr * 2 + 1], qf[ks], &kq[2]);
            }
        }

        float mx0 = -1e30f, mx1 = -1e30f;
#pragma unroll
        for (int nt = 0; nt < 8; nt++) {
            mx0 = fmaxf(mx0, fmaxf(sacc[nt][0], sacc[nt][1]));
            mx1 = fmaxf(mx1, fmaxf(sacc[nt][2], sacc[nt][3]));
        }
        mx0 = fmaxf(mx0, __shfl_xor_sync(0xFFFFFFFFu, mx0, 1));
        mx0 = fmaxf(mx0, __shfl_xor_sync(0xFFFFFFFFu, mx0, 2));
        mx1 = fmaxf(mx1, __shfl_xor_sync(0xFFFFFFFFu, mx1, 1));
        mx1 = fmaxf(mx1, __shfl_xor_sync(0xFFFFFFFFu, mx1, 2));
        float mn0 = fmaxf(m0, mx0), mn1 = fmaxf(m1, mx1);
        float c0 = __expf(m0 - mn0), c1 = __expf(m1 - mn1);
        m0 = mn0; m1 = mn1;
        l0 *= c0;  l1 *= c1;
#pragma unroll
        for (int nt = 0; nt < 8; nt++) {
            ctx[nt][0] *= c0; ctx[nt][1] *= c0;
            ctx[nt][2] *= c1; ctx[nt][3] *= c1;
        }
#pragma unroll
        for (int nt = 0; nt < 8; nt++) {
            float p00 = __expf(sacc[nt][0] - mn0);
            float p01 = __expf(sacc[nt][1] - mn0);
            float p10 = __expf(sacc[nt][2] - mn1);
            float p11 = __expf(sacc[nt][3] - mn1);
            l0 += p00 + p01;
            l1 += p10 + p11;
            int c = nt * 8 + 2 * t4;
            *(float2*)(pw + g * KSTR + c)       = make_float2(to_tf32(p00), to_tf32(p01));
            *(float2*)(pw + (g + 8) * KSTR + c) = make_float2(to_tf32(p10), to_tf32(p11));
        }
        __syncwarp();

#pragma unroll
        for (int ks = 0; ks < 8; ks++) {
            int k = ks * 8;
            uint32_t af[4];
            ldmx4(af, p_lm + ks * 32);
#pragma unroll
            for (int nt = 0; nt < 8; nt++) {
                uint32_t bf[2];
                bf[0] = __float_as_uint(Vs[(k + t4) * VSTR + nt * 8 + g]);
                bf[1] = __float_as_uint(Vs[(k + t4 + 4) * VSTR + nt * 8 + g]);
                mma_tf32(ctx[nt], af, bf);
            }
        }
        __syncwarp();
    }

    l0 += __shfl_xor_sync(0xFFFFFFFFu, l0, 1);
    l0 += __shfl_xor_sync(0xFFFFFFFFu, l0, 2);
    l1 += __shfl_xor_sync(0xFFFFFFFFu, l1, 1);
    l1 += __shfl_xor_sync(0xFFFFFFFFu, l1, 2);
    float inv0 = 1.0f / l0, inv1 = 1.0f / l1;
    int s0 = q0 + wid * 16 + g;
    int b  = bh >> 4;
    int h  = bh & 15;
    __half* o0 = g_ctx + ((size_t)(s0 * B_ + b) * D_ + h * HD_);
    __half* o1 = g_ctx + ((size_t)((s0 + 8) * B_ + b) * D_ + h * HD_);
#pragma unroll
    for (int nt = 0; nt < 8; nt++) {
        int c = nt * 8 + 2 * t4;
        *(__half2*)(o0 + c) = __floats2half2_rn(ctx[nt][0] * inv0, ctx[nt][1] * inv0);
        *(__half2*)(o1 + c) = __floats2half2_rn(ctx[nt][2] * inv1, ctx[nt][3] * inv1);
    }
}

// ---------------- launch ----------------
extern "C" void kernel_launch(void* const* d_in, const int* in_sizes, int n_in,
                              void* d_out, int out_size)
{
    const float* src       = (const float*)d_in[0];
    const float* pos       = (const float*)d_in[1];
    const float* in_proj_w = (const float*)d_in[2];
    const float* alpha_in  = (const float*)d_in[3];
    const float* out_projw = (const float*)d_in[4];
    const float* alpha_out = (const float*)d_in[5];
    const float* w1        = (const float*)d_in[6];
    const float* b1        = (const float*)d_in[7];
    const float* alpha1    = (const float*)d_in[8];
    const float* w2        = (const float*)d_in[9];
    const float* b2        = (const float*)d_in[10];
    const float* alpha2    = (const float*)d_in[11];
    const float* ln1_g     = (const float*)d_in[12];
    const float* ln1_b     = (const float*)d_in[13];
    const float* ln2_g     = (const float*)d_in[14];
    const float* ln2_b     = (const float*)d_in[15];
    float* out = (float*)d_out;

    __half *p_src2, *p_qk, *p_ctx, *p_src2b, *p_h, *p_wi, *p_wo, *p_w1, *p_w2;
    float  *p_res1, *p_al;
    cudaGetSymbolAddress((void**)&p_src2,  g_src2);
    cudaGetSymbolAddress((void**)&p_qk,    g_qk);
    cudaGetSymbolAddress((void**)&p_ctx,   g_ctx);
    cudaGetSymbolAddress((void**)&p_res1,  g_res1);
    cudaGetSymbolAddress((void**)&p_src2b, g_src2b);
    cudaGetSymbolAddress((void**)&p_h,     g_h);
    cudaGetSymbolAddress((void**)&p_al,    g_alphas);
    cudaGetSymbolAddress((void**)&p_wi,    g_wi);
    cudaGetSymbolAddress((void**)&p_wo,    g_wo);
    cudaGetSymbolAddress((void**)&p_w1,    g_w1);
    cudaGetSymbolAddress((void**)&p_w2,    g_w2);

    cudaFuncSetAttribute(mma_gemm<0>, cudaFuncAttributeMaxDynamicSharedMemorySize, SM_TOTAL);
    cudaFuncSetAttribute(mma_gemm<1>, cudaFuncAttributeMaxDynamicSharedMemorySize, SM_TOTAL);
    cudaFuncSetAttribute(mma_gemm<2>, cudaFuncAttributeMaxDynamicSharedMemorySize, SM_TOTAL);
    cudaFuncSetAttribute(mma_gemm<3>, cudaFuncAttributeMaxDynamicSharedMemorySize, SM_TOTAL);
    cudaFuncSetAttribute(attn_mma_kernel, cudaFuncAttributeMaxDynamicSharedMemorySize, ASM_TOTAL);

    // quantize all 4 weight matrices -> fp16 integers (exact)
    {
        int n4 = (NWI + NWO + NW1 + NW2) / 4;
        quant_all_kernel<<<(n4 + 255) / 256, 256>>>(in_proj_w, alpha_in, out_projw, alpha_out,
                                                    w1, alpha1, w2, alpha2);
    }

    // LN1 -> src2 (fp16), qk = src2 + pos (fp16)
    ln_kernel<<<NTOK, 256>>>(src, pos, ln1_g, ln1_b, p_src2, p_qk);

    // QKV projection (fp16 mma), scattered to [B,H,S,HD] fp32/tf32
    mma_gemm<0><<<dim3(3 * D_ / 128, NTOK / 128), 256, SM_TOTAL>>>(
        p_qk, p_src2, p_wi, nullptr, nullptr, nullptr, D_, 3 * D_, p_al + 0);

    // attention (tf32 flash) -> g_ctx fp16
    attn_mma_kernel<<<dim3(S_ / 128, B_ * H_), 256, ASM_TOTAL>>>();

    // out_proj + residual(src) -> res1 (fp32)
    mma_gemm<1><<<dim3(D_ / 128, NTOK / 128), 256, SM_TOTAL>>>(
        p_ctx, nullptr, p_wo, nullptr, src, p_res1, D_, D_, p_al + 1);

    // LN2 -> src2b (fp16)
    ln_kernel<<<NTOK, 256>>>(p_res1, nullptr, ln2_g, ln2_b, p_src2b, nullptr);

    // FFN1: relu(src2b @ w1^T + b1) -> h (fp16)
    mma_gemm<2><<<dim3(DFF_ / 128, NTOK / 128), 256, SM_TOTAL>>>(
        p_src2b, nullptr, p_w1, b1, nullptr, p_h, D_, DFF_, p_al + 2);

    // FFN2: res1 + h @ w2^T + b2 -> out (fp32)
    mma_gemm<3><<<dim3(D_ / 128, NTOK / 128), 256, SM_TOTAL>>>(
        p_h, nullptr, p_w2, b2, p_res1, out, DFF_, D_, p_al + 3);
}

// round 12
// speedup vs baseline: 1.6831x; 1.0005x over previous
#include <cuda_runtime.h>
#include <cuda_fp16.h>
#include <cmath>
#include <cstdint>

#define S_   1024
#define B_   4
#define D_   1024
#define H_   16
#define HD_  64
#define DFF_ 4096
#define NTOK 4096   // S_*B_

// ---------------- device-global scratch (no allocations allowed) ----------------
__device__ __half g_src2 [NTOK * D_];    // LN1(src)           (fp16)
__device__ __half g_qk   [NTOK * D_];    // LN1(src) + pos     (fp16)
__device__ float  g_q    [NTOK * D_];    // [B,H,S,HD], alpha/8 folded, tf32
__device__ float  g_k    [NTOK * D_];    // [B,H,S,HD], tf32
__device__ float  g_v    [NTOK * D_];    // [B,H,S,HD], tf32
__device__ __half g_ctx  [NTOK * D_];    // attention output, [S,B,D] (fp16)
__device__ float  g_res1 [NTOK * D_];    // src + attn_out (fp32 residual)
__device__ __half g_src2b[NTOK * D_];    // LN2(res1)          (fp16)
__device__ __half g_h    [NTOK * DFF_];  // relu(ffn1)         (fp16)
__device__ __half g_wi   [3 * D_ * D_];  // quantized in_proj_w  (exact ints)
__device__ __half g_wo   [D_ * D_];      // quantized out_proj_w (exact ints)
__device__ __half g_w1   [DFF_ * D_];    // quantized w1         (exact ints)
__device__ __half g_w2   [D_ * DFF_];    // quantized w2         (exact ints)
__device__ float  g_alphas[4];           // effective LSQ scales (in, out, w1, w2)

// ================= helpers =================
__device__ __forceinline__ uint32_t smem_u32(const void* p) {
    uint32_t a;
    asm("{ .reg .u64 t; cvta.to.shared.u64 t, %1; cvt.u32.u64 %0, t; }" : "=r"(a) : "l"(p));
    return a;
}
__device__ __forceinline__ float to_tf32(float x) {
    uint32_t r;
    asm("cvt.rna.tf32.f32 %0, %1;" : "=r"(r) : "f"(x));
    return __uint_as_float(r);
}
__device__ __forceinline__ void cp_async16(uint32_t saddr, const void* gaddr) {
    asm volatile("cp.async.cg.shared.global [%0], [%1], 16;" :: "r"(saddr), "l"(gaddr));
}
#define CP_COMMIT()  asm volatile("cp.async.commit_group;" ::: "memory")
#define CP_WAIT(n)   asm volatile("cp.async.wait_group %0;" :: "n"(n) : "memory")

// mma.sync m16n8k16 fp16 with fp32 accumulate (baseline sm_80+)
__device__ __forceinline__ void mma_f16(float* d, const uint32_t* a, const uint32_t* b) {
    asm volatile(
        "mma.sync.aligned.m16n8k16.row.col.f32.f16.f16.f32 "
        "{%0,%1,%2,%3}, {%4,%5,%6,%7}, {%8,%9}, {%0,%1,%2,%3};"
        : "+f"(d[0]), "+f"(d[1]), "+f"(d[2]), "+f"(d[3])
        : "r"(a[0]), "r"(a[1]), "r"(a[2]), "r"(a[3]), "r"(b[0]), "r"(b[1]));
}
// mma.sync m16n8k8 tf32 (attention path)
__device__ __forceinline__ void mma_tf32(float* d, const uint32_t* a, const uint32_t* b) {
    asm volatile(
        "mma.sync.aligned.m16n8k8.row.col.f32.tf32.tf32.f32 "
        "{%0,%1,%2,%3}, {%4,%5,%6,%7}, {%8,%9}, {%0,%1,%2,%3};"
        : "+f"(d[0]), "+f"(d[1]), "+f"(d[2]), "+f"(d[3])
        : "r"(a[0]), "r"(a[1]), "r"(a[2]), "r"(a[3]), "r"(b[0]), "r"(b[1]));
}
__device__ __forceinline__ void ldmx4(uint32_t* r, uint32_t addr) {
    asm volatile("ldmatrix.sync.aligned.m8n8.x4.shared.b16 {%0,%1,%2,%3}, [%4];"
        : "=r"(r[0]), "=r"(r[1]), "=r"(r[2]), "=r"(r[3]) : "r"(addr));
}

// ---------------- LSQ weight quantization: all 4 matrices, one launch ----------------
#define NWI (3 * D_ * D_)
#define NWO (D_ * D_)
#define NW1 (DFF_ * D_)
#define NW2 (D_ * DFF_)
__global__ void quant_all_kernel(
    const float* __restrict__ wi, const float* __restrict__ ai,
    const float* __restrict__ wo, const float* __restrict__ ao,
    const float* __restrict__ w1, const float* __restrict__ a1,
    const float* __restrict__ w2, const float* __restrict__ a2)
{
    int i = blockIdx.x * blockDim.x + threadIdx.x;     // float4 index
    const float* w; const float* alp; __half* out; float gg; int slot; int li;
    if (i < NWI / 4) {
        w = wi; alp = ai; out = g_wi; li = i; slot = 0;
        gg = 2.1308894e-4f;
    } else if (i < (NWI + NWO) / 4) {
        w = wo; alp = ao; out = g_wo; li = i - NWI / 4; slot = 1;
        gg = 3.6908489e-4f;
    } else if (i < (NWI + NWO + NW1) / 4) {
        w = w1; alp = a1; out = g_w1; li = i - (NWI + NWO) / 4; slot = 2;
        gg = 1.8454244e-4f;
    } else if (i < (NWI + NWO + NW1 + NW2) / 4) {
        w = w2; alp = a2; out = g_w2; li = i - (NWI + NWO + NW1) / 4; slot = 3;
        gg = 1.8454244e-4f;
    } else return;
    float al = alp[0];
    float ag = al * gg;
    float a  = ag + (al - ag);
    float inv = 1.0f / a;
    float4 v = ((const float4*)w)[li];
    float qx = rintf(fminf(fmaxf(v.x * inv, -8.0f), 7.0f));
    float qy = rintf(fminf(fmaxf(v.y * inv, -8.0f), 7.0f));
    float qz = rintf(fminf(fmaxf(v.z * inv, -8.0f), 7.0f));
    float qw = rintf(fminf(fmaxf(v.w * inv, -8.0f), 7.0f));
    __half2 h01 = __floats2half2_rn(qx, qy);
    __half2 h23 = __floats2half2_rn(qz, qw);
    uint2 u;
    u.x = *(const uint32_t*)&h01;
    u.y = *(const uint32_t*)&h23;
    ((uint2*)out)[li] = u;
    if (li == 0) g_alphas[slot] = a;
}

// ---------------- LayerNorm (one block per row of 1024); fp16 outputs ----------------
__global__ __launch_bounds__(256) void ln_kernel(
    const float* __restrict__ x, const float* __restrict__ pos,
    const float* __restrict__ gamma, const float* __restrict__ beta,
    __half* __restrict__ y, __half* __restrict__ yp)
{
    int row = blockIdx.x;
    int t   = threadIdx.x;
    const float4* xr = (const float4*)(x + (size_t)row * D_);
    float4 v = xr[t];
    float s  = v.x + v.y + v.z + v.w;
    float ss = v.x * v.x + v.y * v.y + v.z * v.z + v.w * v.w;
#pragma unroll
    for (int o = 16; o > 0; o >>= 1) {
        s  += __shfl_xor_sync(0xFFFFFFFFu, s,  o);
        ss += __shfl_xor_sync(0xFFFFFFFFu, ss, o);
    }
    __shared__ float ws[8], wss[8], fin[2];
    int w = t >> 5;
    if ((t & 31) == 0) { ws[w] = s; wss[w] = ss; }
    __syncthreads();
    if (t == 0) {
        float a = 0.f, b = 0.f;
#pragma unroll
        for (int i = 0; i < 8; i++) { a += ws[i]; b += wss[i]; }
        float m   = a * (1.0f / D_);
        float var = b * (1.0f / D_) - m * m;
        fin[0] = m;
        fin[1] = rsqrtf(var + 1e-5f);
    }
    __syncthreads();
    float m = fin[0], r = fin[1];
    float4 g4 = ((const float4*)gamma)[t];
    float4 b4 = ((const float4*)beta)[t];
    float4 o;
    o.x = (v.x - m) * r * g4.x + b4.x;
    o.y = (v.y - m) * r * g4.y + b4.y;
    o.z = (v.z - m) * r * g4.z + b4.z;
    o.w = (v.w - m) * r * g4.w + b4.w;
    {
        __half2 h01 = __floats2half2_rn(o.x, o.y);
        __half2 h23 = __floats2half2_rn(o.z, o.w);
        uint2 u; u.x = *(const uint32_t*)&h01; u.y = *(const uint32_t*)&h23;
        ((uint2*)(y + (size_t)row * D_))[t] = u;
    }
    if (yp) {
        float4 p = ((const float4*)(pos + (size_t)row * D_))[t];
        __half2 h01 = __floats2half2_rn(o.x + p.x, o.y + p.y);
        __half2 h23 = __floats2half2_rn(o.z + p.z, o.w + p.w);
        uint2 u; u.x = *(const uint32_t*)&h01; u.y = *(const uint32_t*)&h23;
        ((uint2*)(yp + (size_t)row * D_))[t] = u;
    }
}

// =============== fp16 mma.sync GEMM: C = scale * (A[M,K] @ W[Nn,K]^T) + epi ===============
// CTA tile 128x128, BK=64 halfs, 8 warps (2x4), warp tile 64x32, 3-stage single-barrier pipeline.
// Smem row = 64 halfs (128B) padded to 144B; 36r mod 32 = {0,4,..,28} -> ldmatrix conflict-free.
#define SROW_B  144                      // bytes per smem row
#define ATILE   (128 * SROW_B)           // 18432 B per tile
#define STAGE   (2 * ATILE)              // 36864 B
#define NSTAGE  3
#define SM_TOTAL (NSTAGE * STAGE)        // 110592 B

template <int EPI>
__global__ __launch_bounds__(256) void mma_gemm(
    const __half* __restrict__ A, const __half* __restrict__ A2,
    const __half* __restrict__ W, const float* __restrict__ bias,
    const float* __restrict__ resid, void* __restrict__ Cv,
    int K, int Nn, const float* __restrict__ alpha)
{
    extern __shared__ char smem[];
    uint32_t sb = smem_u32(smem);
    int tid = threadIdx.x;
    int wid = tid >> 5;
    int lane = tid & 31;
    int g  = lane >> 2;
    int t4 = lane & 3;
    int q3 = lane >> 3;
    int rin = lane & 7;
    int warp_m = wid >> 2;
    int warp_n = wid & 3;

    int brow = blockIdx.y * 128;
    int bcol = blockIdx.x * 128;
    const __half* Ain = (EPI == 0 && bcol >= 2 * D_) ? A2 : A;

    // cp.async mapping: thread t -> tile row t>>1, 64B half (t&1), 4x16B each
    int lrow = tid >> 1;
    int lhalf = tid & 1;
    const __half* agp = Ain + (size_t)(brow + lrow) * K + lhalf * 32;
    const __half* wgp = W   + (size_t)(bcol + lrow) * K + lhalf * 32;
    uint32_t sa = sb + lrow * SROW_B + lhalf * 64;
    uint32_t sw = sa + ATILE;

    // ldmatrix per-lane bases
    // A m16k16 frags: row + (q3&1)*8, kcol + (q3>>1)*16B
    uint32_t a_lm = sb + (warp_m * 64 + (q3 & 1) * 8 + rin) * SROW_B + (q3 >> 1) * 16;
    // B n16k16 (two n8k16 frags): row n + (q3>>1)*8, kcol + (q3&1)*16B
    uint32_t b_lm = sb + ATILE + (warp_n * 32 + (q3 >> 1) * 8 + rin) * SROW_B + (q3 & 1) * 16;

    float acc[4][4][4];
#pragma unroll
    for (int i = 0; i < 4; i++)
#pragma unroll
        for (int j = 0; j < 4; j++)
#pragma unroll
            for (int e = 0; e < 4; e++) acc[i][j][e] = 0.f;

    const int nch = K / 64;

#define ISSUE(c, s) do {                                              \
        int k0_ = (c) * 64;                                           \
        uint32_t so_ = (uint32_t)(s) * STAGE;                         \
        _Pragma("unroll")                                             \
        for (int q_ = 0; q_ < 4; q_++) {                              \
            cp_async16(sa + so_ + q_ * 16, agp + k0_ + q_ * 8);       \
            cp_async16(sw + so_ + q_ * 16, wgp + k0_ + q_ * 8);       \
        }                                                             \
    } while (0)

    ISSUE(0, 0); CP_COMMIT();
    ISSUE(1, 1); CP_COMMIT();
    CP_WAIT(1);
    __syncthreads();

    for (int i = 0; i < nch; i++) {
        if (i + 2 < nch) ISSUE(i + 2, (i + 2) % NSTAGE);
        CP_COMMIT();

        int s = i % NSTAGE;
        uint32_t ab = a_lm + (uint32_t)s * STAGE;
        uint32_t bb = b_lm + (uint32_t)s * STAGE;
#pragma unroll
        for (int ks = 0; ks < 4; ks++) {         // 4 k16 steps per 64-half chunk
            uint32_t af[4][4], bq[2][4];
#pragma unroll
            for (int mt = 0; mt < 4; mt++)
                ldmx4(af[mt], ab + mt * (16 * SROW_B) + ks * 32);
#pragma unroll
            for (int pr = 0; pr < 2; pr++)
                ldmx4(bq[pr], bb + pr * (16 * SROW_B) + ks * 32);
#pragma unroll
            for (int mt = 0; mt < 4; mt++) {
                mma_f16(acc[mt][0], af[mt], &bq[0][0]);
                mma_f16(acc[mt][1], af[mt], &bq[0][2]);
                mma_f16(acc[mt][2], af[mt], &bq[1][0]);
                mma_f16(acc[mt][3], af[mt], &bq[1][2]);
            }
        }

        CP_WAIT(1);
        __syncthreads();
    }
#undef ISSUE

    float scale = __ldg(alpha);
#pragma unroll
    for (int mt = 0; mt < 4; mt++) {
        int r0 = brow + warp_m * 64 + mt * 16 + g;
#pragma unroll
        for (int half = 0; half < 2; half++) {
            int rr = r0 + half * 8;
#pragma unroll
            for (int nt = 0; nt < 4; nt++) {
                int c = bcol + warp_n * 32 + nt * 8 + t4 * 2;
                float v0 = acc[mt][nt][half * 2 + 0];
                float v1 = acc[mt][nt][half * 2 + 1];
                if (EPI == 0) {
                    int region = bcol >> 10;
                    float sc = (region == 0) ? scale * 0.125f : scale;
                    float* dst0 = (region == 0) ? g_q : (region == 1) ? g_k : g_v;
                    int s  = rr >> 2;
                    int bb = rr & 3;
                    int cd = c & 1023;
                    int h  = cd >> 6, d = cd & 63;
                    float2 o = make_float2(to_tf32(v0 * sc), to_tf32(v1 * sc));
                    *(float2*)(dst0 + (((size_t)bb * H_ + h) * S_ + s) * HD_ + d) = o;
                } else if (EPI == 2) {
                    // relu + bias -> fp16 h
                    float2 bb = *(const float2*)(bias + c);
                    v0 = fmaxf(v0 * scale + bb.x, 0.f);
                    v1 = fmaxf(v1 * scale + bb.y, 0.f);
                    *(__half2*)((__half*)Cv + (size_t)rr * Nn + c) = __floats2half2_rn(v0, v1);
                } else {
                    float* crow = (float*)Cv + (size_t)rr * Nn + c;
                    v0 *= scale; v1 *= scale;
                    if (EPI == 3) {
                        float2 bb = *(const float2*)(bias + c);
                        float2 rv = *(const float2*)(resid + (size_t)rr * Nn + c);
                        v0 += bb.x + rv.x; v1 += bb.y + rv.y;
                    }
                    if (EPI == 1) {
                        float2 rv = *(const float2*)(resid + (size_t)rr * Nn + c);
                        v0 += rv.x; v1 += rv.y;
                    }
                    *(float2*)crow = make_float2(v0, v1);
                }
            }
        }
    }
}

// =============== Flash attention on mma.sync tf32 + ldmatrix (unchanged math) ===============
#define KSTR 68
#define VSTR 72
#define ASM_K 0
#define ASM_V (64 * KSTR)
#define ASM_P (64 * KSTR + 64 * VSTR)
#define ASM_TOTAL ((64 * KSTR + 64 * VSTR + 128 * KSTR) * 4)

__global__ __launch_bounds__(256) void attn_mma_kernel()
{
    extern __shared__ float sm[];
    float* Ks = sm + ASM_K;
    float* Vs = sm + ASM_V;
    float* Ps = sm + ASM_P;
    uint32_t sb = smem_u32(sm);

    int tid  = threadIdx.x;
    int wid  = tid >> 5;
    int lane = tid & 31;
    int g    = lane >> 2;
    int t4   = lane & 3;
    int q3   = lane >> 3;
    int rin  = lane & 7;
    int bh   = blockIdx.y;
    int q0   = blockIdx.x * 128;

    const float* Qb = g_q + ((size_t)bh * S_ + q0 + wid * 16) * HD_;
    uint32_t qf[8][4];
#pragma unroll
    for (int ks = 0; ks < 8; ks++) {
        qf[ks][0] = __float_as_uint(Qb[g * HD_ + ks * 8 + t4]);
        qf[ks][1] = __float_as_uint(Qb[(g + 8) * HD_ + ks * 8 + t4]);
        qf[ks][2] = __float_as_uint(Qb[g * HD_ + ks * 8 + t4 + 4]);
        qf[ks][3] = __float_as_uint(Qb[(g + 8) * HD_ + ks * 8 + t4 + 4]);
    }

    float ctx[8][4];
#pragma unroll
    for (int nt = 0; nt < 8; nt++)
#pragma unroll
        for (int e = 0; e < 4; e++) ctx[nt][e] = 0.f;
    float m0 = -1e30f, m1 = -1e30f, l0 = 0.f, l1 = 0.f;

    const float* kbase = g_k + (size_t)bh * S_ * HD_;
    const float* vbase = g_v + (size_t)bh * S_ * HD_;
    float* pw = Ps + (wid * 16) * KSTR;

    uint32_t k_lm = sb + (ASM_K + ((q3 >> 1) * 8 + rin) * KSTR) * 4 + (q3 & 1) * 16;
    uint32_t p_lm = sb + (ASM_P + (wid * 16 + (q3 & 1) * 8 + rin) * KSTR) * 4 + (q3 >> 1) * 16;

    for (int kt = 0; kt < 16; kt++) {
        __syncthreads();
#pragma unroll
        for (int i = 0; i < 4; i++) {
            int idx = i * 256 + tid;
            int r = idx >> 4, c4 = (idx & 15) * 4;
            *(float4*)(Ks + r * KSTR + c4) =
                *(const float4*)(kbase + (size_t)(kt * 64 + r) * HD_ + c4);
            *(float4*)(Vs + r * VSTR + c4) =
                *(const float4*)(vbase + (size_t)(kt * 64 + r) * HD_ + c4);
        }
        __syncthreads();

        float sacc[8][4];
#pragma unroll
        for (int nt = 0; nt < 8; nt++)
#pragma unroll
            for (int e = 0; e < 4; e++) sacc[nt][e] = 0.f;
#pragma unroll
        for (int ks = 0; ks < 8; ks++) {
#pragma unroll
            for (int pr = 0; pr < 4; pr++) {
                uint32_t kq[4];
                ldmx4(kq, k_lm + pr * (16 * KSTR * 4) + ks * 32);
                mma_tf32(sacc[pr * 2 + 0], qf[ks], &kq[0]);
                mma_tf32(sacc[pr * 2 + 1], qf[ks], &kq[2]);
            }
        }

        float mx0 = -1e30f, mx1 = -1e30f;
#pragma unroll
        for (int nt = 0; nt < 8; nt++) {
            mx0 = fmaxf(mx0, fmaxf(sacc[nt][0], sacc[nt][1]));
            mx1 = fmaxf(mx1, fmaxf(sacc[nt][2], sacc[nt][3]));
        }
        mx0 = fmaxf(mx0, __shfl_xor_sync(0xFFFFFFFFu, mx0, 1));
        mx0 = fmaxf(mx0, __shfl_xor_sync(0xFFFFFFFFu, mx0, 2));
        mx1 = fmaxf(mx1, __shfl_xor_sync(0xFFFFFFFFu, mx1, 1));
        mx1 = fmaxf(mx1, __shfl_xor_sync(0xFFFFFFFFu, mx1, 2));
        float mn0 = fmaxf(m0, mx0), mn1 = fmaxf(m1, mx1);
        float c0 = __expf(m0 - mn0), c1 = __expf(m1 - mn1);
        m0 = mn0; m1 = mn1;
        l0 *= c0;  l1 *= c1;
#pragma unroll
        for (int nt = 0; nt < 8; nt++) {
            ctx[nt][0] *= c0; ctx[nt][1] *= c0;
            ctx[nt][2] *= c1; ctx[nt][3] *= c1;
        }
#pragma unroll
        for (int nt = 0; nt < 8; nt++) {
            float p00 = __expf(sacc[nt][0] - mn0);
            float p01 = __expf(sacc[nt][1] - mn0);
            float p10 = __expf(sacc[nt][2] - mn1);
            float p11 = __expf(sacc[nt][3] - mn1);
            l0 += p00 + p01;
            l1 += p10 + p11;
            int c = nt * 8 + 2 * t4;
            *(float2*)(pw + g * KSTR + c)       = make_float2(to_tf32(p00), to_tf32(p01));
            *(float2*)(pw + (g + 8) * KSTR + c) = make_float2(to_tf32(p10), to_tf32(p11));
        }
        __syncwarp();

#pragma unroll
        for (int ks = 0; ks < 8; ks++) {
            int k = ks * 8;
            uint32_t af[4];
            ldmx4(af, p_lm + ks * 32);
#pragma unroll
            for (int nt = 0; nt < 8; nt++) {
                uint32_t bf[2];
                bf[0] = __float_as_uint(Vs[(k + t4) * VSTR + nt * 8 + g]);
                bf[1] = __float_as_uint(Vs[(k + t4 + 4) * VSTR + nt * 8 + g]);
                mma_tf32(ctx[nt], af, bf);
            }
        }
        __syncwarp();
    }

    l0 += __shfl_xor_sync(0xFFFFFFFFu, l0, 1);
    l0 += __shfl_xor_sync(0xFFFFFFFFu, l0, 2);
    l1 += __shfl_xor_sync(0xFFFFFFFFu, l1, 1);
    l1 += __shfl_xor_sync(0xFFFFFFFFu, l1, 2);
    float inv0 = 1.0f / l0, inv1 = 1.0f / l1;
    int s0 = q0 + wid * 16 + g;
    int b  = bh >> 4;
    int h  = bh & 15;
    __half* o0 = g_ctx + ((size_t)(s0 * B_ + b) * D_ + h * HD_);
    __half* o1 = g_ctx + ((size_t)((s0 + 8) * B_ + b) * D_ + h * HD_);
#pragma unroll
    for (int nt = 0; nt < 8; nt++) {
        int c = nt * 8 + 2 * t4;
        *(__half2*)(o0 + c) = __floats2half2_rn(ctx[nt][0] * inv0, ctx[nt][1] * inv0);
        *(__half2*)(o1 + c) = __floats2half2_rn(ctx[nt][2] * inv1, ctx[nt][3] * inv1);
    }
}

// ---------------- launch ----------------
extern "C" void kernel_launch(void* const* d_in, const int* in_sizes, int n_in,
                              void* d_out, int out_size)
{
    const float* src       = (const float*)d_in[0];
    const float* pos       = (const float*)d_in[1];
    const float* in_proj_w = (const float*)d_in[2];
    const float* alpha_in  = (const float*)d_in[3];
    const float* out_projw = (const float*)d_in[4];
    const float* alpha_out = (const float*)d_in[5];
    const float* w1        = (const float*)d_in[6];
    const float* b1        = (const float*)d_in[7];
    const float* alpha1    = (const float*)d_in[8];
    const float* w2        = (const float*)d_in[9];
    const float* b2        = (const float*)d_in[10];
    const float* alpha2    = (const float*)d_in[11];
    const float* ln1_g     = (const float*)d_in[12];
    const float* ln1_b     = (const float*)d_in[13];
    const float* ln2_g     = (const float*)d_in[14];
    const float* ln2_b     = (const float*)d_in[15];
    float* out = (float*)d_out;

    __half *p_src2, *p_qk, *p_ctx, *p_src2b, *p_h, *p_wi, *p_wo, *p_w1, *p_w2;
    float  *p_res1, *p_al;
    cudaGetSymbolAddress((void**)&p_src2,  g_src2);
    cudaGetSymbolAddress((void**)&p_qk,    g_qk);
    cudaGetSymbolAddress((void**)&p_ctx,   g_ctx);
    cudaGetSymbolAddress((void**)&p_res1,  g_res1);
    cudaGetSymbolAddress((void**)&p_src2b, g_src2b);
    cudaGetSymbolAddress((void**)&p_h,     g_h);
    cudaGetSymbolAddress((void**)&p_al,    g_alphas);
    cudaGetSymbolAddress((void**)&p_wi,    g_wi);
    cudaGetSymbolAddress((void**)&p_wo,    g_wo);
    cudaGetSymbolAddress((void**)&p_w1,    g_w1);
    cudaGetSymbolAddress((void**)&p_w2,    g_w2);

    cudaFuncSetAttribute(mma_gemm<0>, cudaFuncAttributeMaxDynamicSharedMemorySize, SM_TOTAL);
    cudaFuncSetAttribute(mma_gemm<1>, cudaFuncAttributeMaxDynamicSharedMemorySize, SM_TOTAL);
    cudaFuncSetAttribute(mma_gemm<2>, cudaFuncAttributeMaxDynamicSharedMemorySize, SM_TOTAL);
    cudaFuncSetAttribute(mma_gemm<3>, cudaFuncAttributeMaxDynamicSharedMemorySize, SM_TOTAL);
    cudaFuncSetAttribute(attn_mma_kernel, cudaFuncAttributeMaxDynamicSharedMemorySize, ASM_TOTAL);

    // quantize all 4 weight matrices -> fp16 integers (exact)
    {
        int n4 = (NWI + NWO + NW1 + NW2) / 4;
        quant_all_kernel<<<(n4 + 255) / 256, 256>>>(in_proj_w, alpha_in, out_projw, alpha_out,
                                                    w1, alpha1, w2, alpha2);
    }

    // LN1 -> src2 (fp16), qk = src2 + pos (fp16)
    ln_kernel<<<NTOK, 256>>>(src, pos, ln1_g, ln1_b, p_src2, p_qk);

    // QKV projection (fp16 mma), scattered to [B,H,S,HD] fp32/tf32
    mma_gemm<0><<<dim3(3 * D_ / 128, NTOK / 128), 256, SM_TOTAL>>>(
        p_qk, p_src2, p_wi, nullptr, nullptr, nullptr, D_, 3 * D_, p_al + 0);

    // attention (tf32 flash) -> g_ctx fp16
    attn_mma_kernel<<<dim3(S_ / 128, B_ * H_), 256, ASM_TOTAL>>>();

    // out_proj + residual(src) -> res1 (fp32)
    mma_gemm<1><<<dim3(D_ / 128, NTOK / 128), 256, SM_TOTAL>>>(
        p_ctx, nullptr, p_wo, nullptr, src, p_res1, D_, D_, p_al + 1);

    // LN2 -> src2b (fp16)
    ln_kernel<<<NTOK, 256>>>(p_res1, nullptr, ln2_g, ln2_b, p_src2b, nullptr);

    // FFN1: relu(src2b @ w1^T + b1) -> h (fp16)
    mma_gemm<2><<<dim3(DFF_ / 128, NTOK / 128), 256, SM_TOTAL>>>(
        p_src2b, nullptr, p_w1, b1, nullptr, p_h, D_, DFF_, p_al + 2);

    // FFN2: res1 + h @ w2^T + b2 -> out (fp32)
    mma_gemm<3><<<dim3(D_ / 128, NTOK / 128), 256, SM_TOTAL>>>(
        p_h, nullptr, p_w2, b2, p_res1, out, DFF_, D_, p_al + 3);
}